// round 11
// baseline (speedup 1.0000x reference)
#include <cuda_runtime.h>
#include <cuda_fp16.h>
#include <math.h>
#include <stdint.h>

// Problem constants
#define BB 8
#define LL 2048
#define EE 1024
#define HH 16
#define DD 64
#define MROWS (BB*LL)          // 16384
#define EPSF 1e-6f

// Scratch (device globals: allocation-free rule)
__device__ float  g_q[(size_t)MROWS * EE];
__device__ float  g_k[(size_t)MROWS * EE];
__device__ float  g_v[(size_t)MROWS * EE];
__device__ __half g_ah[(size_t)MROWS * EE];      // fp16 attention output (Wo GEMM input)
__device__ __half g_xh[(size_t)MROWS * EE];      // fp16 X
__device__ __half g_wqh[(size_t)EE * EE];        // fp16 transposed weights [N][K]
__device__ __half g_wkh[(size_t)EE * EE];
__device__ __half g_wvh[(size_t)EE * EE];
__device__ __half g_woh[(size_t)EE * EE];
#define PSTRIDE 8320                              // 64*128 kv + 2*64 ksum
__device__ float  g_part[512 * PSTRIDE];          // attn phase-1 partials

// ---------------------------------------------------------------------------
// Conversions
// ---------------------------------------------------------------------------
__global__ __launch_bounds__(256) void conv_x(const float* __restrict__ X)
{
    long long i8 = (long long)blockIdx.x * 256 + threadIdx.x;   // 8 floats each
    long long base = i8 * 8;
    if (base >= (long long)MROWS * EE) return;
    float4 v0 = *(const float4*)(X + base);
    float4 v1 = *(const float4*)(X + base + 4);
    __half2 h[4];
    h[0] = __floats2half2_rn(v0.x, v0.y);
    h[1] = __floats2half2_rn(v0.z, v0.w);
    h[2] = __floats2half2_rn(v1.x, v1.y);
    h[3] = __floats2half2_rn(v1.z, v1.w);
    *(uint4*)(g_xh + base) = *(uint4*)h;
}

// Weight transpose + fp16 round: Wt[n][k] = rn(W[k][n]). 32x32 tiles.
__global__ __launch_bounds__(256) void wtrans_h(
    const float* __restrict__ Wq, const float* __restrict__ Wk,
    const float* __restrict__ Wv, const float* __restrict__ Wo)
{
    __shared__ float t[32][33];
    const float* W; __half* Wt;
    switch (blockIdx.z) {
        case 0: W = Wq; Wt = g_wqh; break;
        case 1: W = Wk; Wt = g_wkh; break;
        case 2: W = Wv; Wt = g_wvh; break;
        default: W = Wo; Wt = g_woh; break;
    }
    int tx = threadIdx.x & 31, ty = threadIdx.x >> 5;   // 32 x 8
    int k0 = blockIdx.y * 32, n0 = blockIdx.x * 32;
#pragma unroll
    for (int i = 0; i < 4; i++)
        t[ty + i * 8][tx] = W[(long long)(k0 + ty + i * 8) * EE + n0 + tx];
    __syncthreads();
#pragma unroll
    for (int i = 0; i < 4; i++)
        Wt[(long long)(n0 + ty + i * 8) * EE + k0 + tx] = __float2half_rn(t[tx][ty + i * 8]);
}

// ---------------------------------------------------------------------------
// fp16 tensor-core GEMM: C = A(MxK) @ Wt(NxK)^T + bias, fp32 accum/output.
// CTA tile 128x256, BK=32 halves, 256 threads (8 warps, each 64x64).
// mma.sync.m16n8k16.f32.f16.f16.f32; 3-stage cp.async pipeline, ONE barrier
// per chunk (wait_group -> sync -> issue next load -> mma).
// smask bit z: apply per-head row softmax (D=64) in the epilogue.
// ---------------------------------------------------------------------------
#define HP 80                     // bytes per smem row
#define ASTG (128*HP)             // 10240
#define BSTG (256*HP)             // 20480
#define STGH (ASTG+BSTG)          // 30720
#define GSMH (3*STGH)             // 92160
#define NCH 32                    // 1024/32 chunks

__device__ __forceinline__ void cp16(void* dst, const void* src) {
    unsigned d = (unsigned)__cvta_generic_to_shared(dst);
    asm volatile("cp.async.cg.shared.global [%0], [%1], 16;\n" :: "r"(d), "l"(src) : "memory");
}

__global__ __launch_bounds__(256, 1) void gemm_h(
    const __half* __restrict__ A,
    const __half* __restrict__ W0, const float* __restrict__ b0, float* __restrict__ C0,
    const __half* __restrict__ W1, const float* __restrict__ b1, float* __restrict__ C1,
    const __half* __restrict__ W2, const float* __restrict__ b2, float* __restrict__ C2,
    int smask)
{
    constexpr int K = EE;
    constexpr int N = EE;
    const __half* Wp = W0; const float* bp = b0; float* Cp = C0;
    if (blockIdx.z == 1) { Wp = W1; bp = b1; Cp = C1; }
    else if (blockIdx.z == 2) { Wp = W2; bp = b2; Cp = C2; }
    const bool do_sm = (smask >> blockIdx.z) & 1;

    extern __shared__ char smc[];

    const int tid = threadIdx.x;
    const int wid = tid >> 5;
    const int lane = tid & 31;
    const int g = lane >> 2;       // 0..7
    const int tg = lane & 3;       // 0..3
    const int wm = wid & 1;
    const int wn = wid >> 1;

    const long long brow = (long long)blockIdx.y * 128;
    const int bcol = blockIdx.x * 256;

    const __half* Abase = A + brow * K;
    const __half* Bbase = Wp + (long long)bcol * K;

    float acc[4][8][4];
#pragma unroll
    for (int mi = 0; mi < 4; mi++)
#pragma unroll
        for (int ni = 0; ni < 8; ni++)
#pragma unroll
            for (int r = 0; r < 4; r++) acc[mi][ni][r] = 0.0f;

    auto load_chunk = [&](int ch) {
        char* As = smc + (ch % 3) * STGH;
        char* Bs = As + ASTG;
        const __half* Ag = Abase + ch * 32;
        const __half* Bg = Bbase + ch * 32;
#pragma unroll
        for (int i = 0; i < 2; i++) {           // A: 128 rows x 4 granules
            int idx = tid + i * 256;
            int r = idx >> 2, c = idx & 3;
            cp16(As + r * HP + c * 16, Ag + (long long)r * K + c * 8);
        }
#pragma unroll
        for (int i = 0; i < 4; i++) {           // B: 256 rows x 4 granules
            int idx = tid + i * 256;
            int r = idx >> 2, c = idx & 3;
            cp16(Bs + r * HP + c * 16, Bg + (long long)r * K + c * 8);
        }
        asm volatile("cp.async.commit_group;\n" ::: "memory");
    };

    load_chunk(0);
    load_chunk(1);

    for (int c = 0; c < NCH; c++) {
        if (c + 1 < NCH) asm volatile("cp.async.wait_group 1;\n" ::: "memory");
        else             asm volatile("cp.async.wait_group 0;\n" ::: "memory");
        __syncthreads();
        // Safe to overwrite stage (c+2)%3 == (c-1)%3: the barrier above proves
        // every warp finished its mma reads of chunk c-1 (issued last iter).
        if (c + 2 < NCH) load_chunk(c + 2);

        const char* As = smc + (c % 3) * STGH;
        const char* Bs = As + ASTG;

#pragma unroll
        for (int s = 0; s < 2; s++) {           // two k16 steps per 32-half chunk
            unsigned af[4][4], bf[8][2];
            int kb = s * 32 + tg * 4;           // byte offset in row
#pragma unroll
            for (int mi = 0; mi < 4; mi++) {
                int m = wm * 64 + mi * 16 + g;
                af[mi][0] = *(const unsigned*)(As + m * HP + kb);
                af[mi][1] = *(const unsigned*)(As + (m + 8) * HP + kb);
                af[mi][2] = *(const unsigned*)(As + m * HP + kb + 16);
                af[mi][3] = *(const unsigned*)(As + (m + 8) * HP + kb + 16);
            }
#pragma unroll
            for (int ni = 0; ni < 8; ni++) {
                int n = wn * 64 + ni * 8 + g;
                bf[ni][0] = *(const unsigned*)(Bs + n * HP + kb);
                bf[ni][1] = *(const unsigned*)(Bs + n * HP + kb + 16);
            }
#pragma unroll
            for (int mi = 0; mi < 4; mi++)
#pragma unroll
                for (int ni = 0; ni < 8; ni++) {
                    asm volatile(
                        "mma.sync.aligned.m16n8k16.row.col.f32.f16.f16.f32 "
                        "{%0,%1,%2,%3}, {%4,%5,%6,%7}, {%8,%9}, {%0,%1,%2,%3};"
                        : "+f"(acc[mi][ni][0]), "+f"(acc[mi][ni][1]),
                          "+f"(acc[mi][ni][2]), "+f"(acc[mi][ni][3])
                        : "r"(af[mi][0]), "r"(af[mi][1]), "r"(af[mi][2]), "r"(af[mi][3]),
                          "r"(bf[ni][0]), "r"(bf[ni][1]));
                }
        }
    }

    // ---- epilogue: bias (+ optional per-head row softmax), write fp32 ----
    float2 bi[8];
#pragma unroll
    for (int ni = 0; ni < 8; ni++)
        bi[ni] = *(const float2*)(bp + bcol + wn * 64 + ni * 8 + 2 * tg);
#pragma unroll
    for (int mi = 0; mi < 4; mi++)
#pragma unroll
        for (int ni = 0; ni < 8; ni++) {
            acc[mi][ni][0] += bi[ni].x; acc[mi][ni][1] += bi[ni].y;
            acc[mi][ni][2] += bi[ni].x; acc[mi][ni][3] += bi[ni].y;
        }

    if (do_sm) {
        // Row softmax over the warp's 64 cols (= one head). Row owned by the
        // lane-quad g*4+{0..3}; shfl_xor 1,2 stay inside the quad.
#pragma unroll
        for (int mi = 0; mi < 4; mi++)
#pragma unroll
            for (int hf = 0; hf < 2; hf++) {
                float mx = -1e30f;
#pragma unroll
                for (int ni = 0; ni < 8; ni++)
                    mx = fmaxf(mx, fmaxf(acc[mi][ni][hf * 2], acc[mi][ni][hf * 2 + 1]));
                mx = fmaxf(mx, __shfl_xor_sync(0xFFFFFFFFu, mx, 1));
                mx = fmaxf(mx, __shfl_xor_sync(0xFFFFFFFFu, mx, 2));
                float sum = 0.0f;
#pragma unroll
                for (int ni = 0; ni < 8; ni++) {
                    float e0 = __expf(acc[mi][ni][hf * 2]     - mx);
                    float e1 = __expf(acc[mi][ni][hf * 2 + 1] - mx);
                    acc[mi][ni][hf * 2] = e0; acc[mi][ni][hf * 2 + 1] = e1;
                    sum += e0 + e1;
                }
                sum += __shfl_xor_sync(0xFFFFFFFFu, sum, 1);
                sum += __shfl_xor_sync(0xFFFFFFFFu, sum, 2);
                float inv = 1.0f / sum;
#pragma unroll
                for (int ni = 0; ni < 8; ni++) {
                    acc[mi][ni][hf * 2] *= inv; acc[mi][ni][hf * 2 + 1] *= inv;
                }
            }
    }

#pragma unroll
    for (int ni = 0; ni < 8; ni++) {
        int col = bcol + wn * 64 + ni * 8 + 2 * tg;
#pragma unroll
        for (int mi = 0; mi < 4; mi++) {
            long long r0 = brow + wm * 64 + mi * 16 + g;
            *(float2*)(Cp + r0 * N + col)       = make_float2(acc[mi][ni][0], acc[mi][ni][1]);
            *(float2*)(Cp + (r0 + 8) * N + col) = make_float2(acc[mi][ni][2], acc[mi][ni][3]);
        }
    }
}

// ---------------------------------------------------------------------------
// Attention phase 1: partial kv (64x128) + ksum (2x64) per (pair, split).
// grid = 512: blockIdx.x = pair*4 + split; split covers 512 rows.
// 128 threads, 8x8 register tile per thread: FMA:LDS-float ratio 4.0
// (was 2.67 at 4x8/256t) -> no longer over the 128B/cyc smem crossbar.
// ---------------------------------------------------------------------------
__global__ __launch_bounds__(128, 1) void attn_p1()
{
    __shared__ float k_s[64 * 64];
    __shared__ float v_s[64 * 64];
    __shared__ float sc_s[64][2];

    const int bx = blockIdx.x;
    const int pair = bx >> 2;
    const int sp = bx & 3;
    const int b = pair >> 4;
    const int h = pair & 15;
    const int tid = threadIdx.x;
    const int tx = tid & 15;       // m-group: 0..15 (8 cols each of 128 combined)
    const int ty = tid >> 4;       // d-group: 0..7  (8 rows each of 64)

    const float* kbase = g_k + ((long long)b * LL) * EE + h * DD;
    const float* vbase = g_v + ((long long)b * LL) * EE + h * DD;

    const float cidx = 1.5707963267948966f / (float)LL;

    float accp[8][8];
#pragma unroll
    for (int i = 0; i < 8; i++)
#pragma unroll
        for (int j = 0; j < 8; j++) accp[i][j] = 0.0f;
    float ks_sin = 0.0f, ks_cos = 0.0f;

    const int mh = (tx & 7) * 8;          // v column base
    const int fsel = (tx < 8) ? 0 : 1;    // sin half vs cos half
    for (int c = 0; c < 8; c++) {
        int l0 = sp * 512 + c * 64;
        if (tid < 64) {
            float s, co;
            __sincosf(cidx * (float)(l0 + tid + 1), &s, &co);
            sc_s[tid][0] = s; sc_s[tid][1] = co;
        }
#pragma unroll
        for (int i = 0; i < 8; i++) {      // 64x64 tiles, 128 threads, f4 loads
            int idx = tid + i * 128;
            int r  = idx >> 4;
            int c4 = idx & 15;
            *(float4*)&k_s[r * 64 + c4 * 4] = *(const float4*)(kbase + (long long)(l0 + r) * EE + c4 * 4);
            *(float4*)&v_s[r * 64 + c4 * 4] = *(const float4*)(vbase + (long long)(l0 + r) * EE + c4 * 4);
        }
        __syncthreads();
#pragma unroll 2
        for (int l = 0; l < 64; l++) {
            float f = sc_s[l][fsel];
            float ra[8], rv[8];
            *(float4*)&ra[0] = *(const float4*)&k_s[l * 64 + ty * 8];
            *(float4*)&ra[4] = *(const float4*)&k_s[l * 64 + ty * 8 + 4];
            *(float4*)&rv[0] = *(const float4*)&v_s[l * 64 + mh];
            *(float4*)&rv[4] = *(const float4*)&v_s[l * 64 + mh + 4];
#pragma unroll
            for (int i = 0; i < 8; i++) {
                float a = ra[i] * f;
#pragma unroll
                for (int j = 0; j < 8; j++)
                    accp[i][j] = fmaf(a, rv[j], accp[i][j]);
            }
        }
        if (tid < 64) {
            for (int l = 0; l < 64; l++) {
                float kd = k_s[l * 64 + tid];
                ks_sin = fmaf(kd, sc_s[l][0], ks_sin);
                ks_cos = fmaf(kd, sc_s[l][1], ks_cos);
            }
        }
        __syncthreads();
    }

    float* part = g_part + (long long)bx * PSTRIDE;
#pragma unroll
    for (int i = 0; i < 8; i++) {
        *(float4*)&part[(ty * 8 + i) * 128 + tx * 8]     = make_float4(accp[i][0], accp[i][1], accp[i][2], accp[i][3]);
        *(float4*)&part[(ty * 8 + i) * 128 + tx * 8 + 4] = make_float4(accp[i][4], accp[i][5], accp[i][6], accp[i][7]);
    }
    if (tid < 64) { part[8192 + tid] = ks_sin; part[8256 + tid] = ks_cos; }
}

// ---------------------------------------------------------------------------
// Attention phase 2: reduce 4 partials, then per-row outputs for one 128-row
// chunk. grid = 2048: blockIdx.x = pair*16 + chunk. Output fp16 into g_ah.
// ---------------------------------------------------------------------------
__global__ __launch_bounds__(256, 1) void attn_p2()
{
    extern __shared__ float sm[];
    __shared__ float ksum_s[2][64];
    __shared__ float vsum_s[128];
    __shared__ float S_s[2];

    const int bx = blockIdx.x;
    const int pair = bx >> 4;
    const int ch = bx & 15;
    const int b = pair >> 4;
    const int h = pair & 15;
    const int tid = threadIdx.x;
    const int tx = tid & 15;
    const int ty = tid >> 4;

    float* kv_s = sm;            // [64][128]
    float* q_s  = sm + 8192;     // [128][64]

    const float* p0 = g_part + (long long)(pair * 4 + 0) * PSTRIDE;
    const float* p1 = g_part + (long long)(pair * 4 + 1) * PSTRIDE;
    const float* p2 = g_part + (long long)(pair * 4 + 2) * PSTRIDE;
    const float* p3 = g_part + (long long)(pair * 4 + 3) * PSTRIDE;

    // reduce kv partials
    for (int t = tid; t < 2048; t += 256) {
        float4 a = *(const float4*)(p0 + t * 4);
        float4 bq = *(const float4*)(p1 + t * 4);
        float4 cq = *(const float4*)(p2 + t * 4);
        float4 dq = *(const float4*)(p3 + t * 4);
        float4 o;
        o.x = a.x + bq.x + cq.x + dq.x;
        o.y = a.y + bq.y + cq.y + dq.y;
        o.z = a.z + bq.z + cq.z + dq.z;
        o.w = a.w + bq.w + cq.w + dq.w;
        *(float4*)&kv_s[t * 4] = o;
    }
    if (tid < 128) {
        float s = p0[8192 + tid] + p1[8192 + tid] + p2[8192 + tid] + p3[8192 + tid];
        ksum_s[tid >> 6][tid & 63] = s;
    }
    __syncthreads();
    if (tid < 128) {
        float s = 0.0f;
        for (int d = 0; d < 64; d++) s += kv_s[d * 128 + tid];
        vsum_s[tid] = s;
    }
    if (tid < 2) {
        float s = 0.0f;
        for (int d = 0; d < 64; d++) s += ksum_s[tid][d];
        S_s[tid] = s;
    }

    // load q chunk
    const float* qbase = g_q + ((long long)b * LL) * EE + h * DD;
    const int l0 = ch * 128;
#pragma unroll
    for (int i = 0; i < 8; i++) {
        int idx = tid + i * 256;
        int r  = idx >> 4;
        int c4 = idx & 15;
        *(float4*)&q_s[r * 64 + c4 * 4] = *(const float4*)(qbase + (long long)(l0 + r) * EE + c4 * 4);
    }
    __syncthreads();

    const float S_sin = S_s[0], S_cos = S_s[1];
    const float cidx = 1.5707963267948966f / (float)LL;

    float ts[8][4], tc2[8][4], us[8], uc[8];
#pragma unroll
    for (int i = 0; i < 8; i++) {
        us[i] = 0.0f; uc[i] = 0.0f;
#pragma unroll
        for (int j = 0; j < 4; j++) { ts[i][j] = 0.0f; tc2[i][j] = 0.0f; }
    }

#pragma unroll 2
    for (int d = 0; d < 64; d++) {
        float rkvs[4], rkvc[4];
        *(float4*)&rkvs[0] = *(const float4*)&kv_s[d * 128 + tx * 4];
        *(float4*)&rkvc[0] = *(const float4*)&kv_s[d * 128 + 64 + tx * 4];
        float kss = ksum_s[0][d], ksc = ksum_s[1][d];
#pragma unroll
        for (int i = 0; i < 8; i++) {
            float qd = q_s[(ty * 8 + i) * 64 + d];
            us[i] = fmaf(qd, kss, us[i]);
            uc[i] = fmaf(qd, ksc, uc[i]);
#pragma unroll
            for (int j = 0; j < 4; j++) {
                ts[i][j]  = fmaf(qd, rkvs[j], ts[i][j]);
                tc2[i][j] = fmaf(qd, rkvc[j], tc2[i][j]);
            }
        }
    }

#pragma unroll
    for (int i = 0; i < 8; i++) {
        int l = l0 + ty * 8 + i;
        float s, co;
        __sincosf(cidx * (float)(l + 1), &s, &co);
        float den1 = fmaf(s, us[i], co * uc[i]);
        float z1 = 1.0f / fmaxf(den1, EPSF);
        float den2 = s * (62.0f * S_sin + us[i]) + co * (62.0f * S_cos + uc[i]);
        float z2 = 1.0f / fmaxf(den2, EPSF);
        float tmp[4];
#pragma unroll
        for (int j = 0; j < 4; j++) {
            int m = tx * 4 + j;
            float n1 = fmaf(s, ts[i][j], co * tc2[i][j]);
            float n2 = s * (62.0f * vsum_s[m] + ts[i][j]) + co * (62.0f * vsum_s[64 + m] + tc2[i][j]);
            tmp[j] = n1 * z1 + n2 * z2;
        }
        __half2 h01 = __floats2half2_rn(tmp[0], tmp[1]);
        __half2 h23 = __floats2half2_rn(tmp[2], tmp[3]);
        __half* op = g_ah + ((long long)l * BB + b) * EE + h * DD + tx * 4;
        uint2 pk;
        pk.x = *(unsigned*)&h01;
        pk.y = *(unsigned*)&h23;
        *(uint2*)op = pk;
    }
}

// ---------------------------------------------------------------------------
extern "C" void kernel_launch(void* const* d_in, const int* in_sizes, int n_in,
                              void* d_out, int out_size)
{
    (void)in_sizes; (void)n_in; (void)out_size;
    const float* X  = (const float*)d_in[0];
    const float* Wq = (const float*)d_in[1];
    const float* bq = (const float*)d_in[2];
    const float* Wk = (const float*)d_in[3];
    const float* bk = (const float*)d_in[4];
    const float* Wv = (const float*)d_in[5];
    const float* bv = (const float*)d_in[6];
    const float* Wo = (const float*)d_in[7];
    const float* bo = (const float*)d_in[8];
    float* out = (float*)d_out;

    float *gq, *gk, *gv;
    __half *gah, *gxh, *gwq, *gwk, *gwv, *gwo;
    cudaGetSymbolAddress((void**)&gq, g_q);
    cudaGetSymbolAddress((void**)&gk, g_k);
    cudaGetSymbolAddress((void**)&gv, g_v);
    cudaGetSymbolAddress((void**)&gah, g_ah);
    cudaGetSymbolAddress((void**)&gxh, g_xh);
    cudaGetSymbolAddress((void**)&gwq, g_wqh);
    cudaGetSymbolAddress((void**)&gwk, g_wkh);
    cudaGetSymbolAddress((void**)&gwv, g_wvh);
    cudaGetSymbolAddress((void**)&gwo, g_woh);

    cudaFuncSetAttribute(gemm_h, cudaFuncAttributeMaxDynamicSharedMemorySize, GSMH);
    cudaFuncSetAttribute(attn_p2, cudaFuncAttributeMaxDynamicSharedMemorySize, 65536);

    // 0) convert X and weights (transposed) to fp16
    conv_x<<<(int)(((long long)MROWS * EE / 8 + 255) / 256), 256>>>(X);
    wtrans_h<<<dim3(32, 32, 4), 256>>>(Wq, Wk, Wv, Wo);

    // 1) fused QKV projections with per-head softmax on q,k in the epilogue
    gemm_h<<<dim3(EE / 256, MROWS / 128, 3), 256, GSMH>>>(
        gxh, gwq, bq, gq, gwk, bk, gk, gwv, bv, gv, 0b011);

    // 2) linear attention: split phase 1 / phase 2 for occupancy
    attn_p1<<<512, 128>>>();
    attn_p2<<<2048, 256, 65536>>>();

    // 3) output projection into d_out (fp16 tensor cores)
    gemm_h<<<dim3(EE / 256, MROWS / 128, 1), 256, GSMH>>>(
        gah, gwo, bo, out, gwo, bo, out, gwo, bo, out, 0);
}

// round 12
// speedup vs baseline: 1.5159x; 1.5159x over previous
#include <cuda_runtime.h>
#include <cuda_fp16.h>
#include <math.h>
#include <stdint.h>

// Problem constants
#define BB 8
#define LL 2048
#define EE 1024
#define HH 16
#define DD 64
#define MROWS (BB*LL)          // 16384
#define EPSF 1e-6f

// Scratch (device globals: allocation-free rule)
__device__ float  g_q[(size_t)MROWS * EE];
__device__ float  g_k[(size_t)MROWS * EE];
__device__ float  g_v[(size_t)MROWS * EE];
__device__ __half g_ah[(size_t)MROWS * EE];      // fp16 attention output (Wo GEMM input)
__device__ __half g_xh[(size_t)MROWS * EE];      // fp16 X
__device__ __half g_wqh[(size_t)EE * EE];        // fp16 transposed weights [N][K]
__device__ __half g_wkh[(size_t)EE * EE];
__device__ __half g_wvh[(size_t)EE * EE];
__device__ __half g_woh[(size_t)EE * EE];
#define SPLITS 8
#define PSTRIDE 8320                              // 64*128 kv + 2*64 ksum
__device__ float  g_part[(size_t)128 * SPLITS * PSTRIDE];   // attn phase-1 partials

// ---------------------------------------------------------------------------
// Conversions
// ---------------------------------------------------------------------------
__global__ __launch_bounds__(256) void conv_x(const float* __restrict__ X)
{
    long long i8 = (long long)blockIdx.x * 256 + threadIdx.x;   // 8 floats each
    long long base = i8 * 8;
    if (base >= (long long)MROWS * EE) return;
    float4 v0 = *(const float4*)(X + base);
    float4 v1 = *(const float4*)(X + base + 4);
    __half2 h[4];
    h[0] = __floats2half2_rn(v0.x, v0.y);
    h[1] = __floats2half2_rn(v0.z, v0.w);
    h[2] = __floats2half2_rn(v1.x, v1.y);
    h[3] = __floats2half2_rn(v1.z, v1.w);
    *(uint4*)(g_xh + base) = *(uint4*)h;
}

// Weight transpose + fp16 round: Wt[n][k] = rn(W[k][n]). 32x32 tiles.
__global__ __launch_bounds__(256) void wtrans_h(
    const float* __restrict__ Wq, const float* __restrict__ Wk,
    const float* __restrict__ Wv, const float* __restrict__ Wo)
{
    __shared__ float t[32][33];
    const float* W; __half* Wt;
    switch (blockIdx.z) {
        case 0: W = Wq; Wt = g_wqh; break;
        case 1: W = Wk; Wt = g_wkh; break;
        case 2: W = Wv; Wt = g_wvh; break;
        default: W = Wo; Wt = g_woh; break;
    }
    int tx = threadIdx.x & 31, ty = threadIdx.x >> 5;   // 32 x 8
    int k0 = blockIdx.y * 32, n0 = blockIdx.x * 32;
#pragma unroll
    for (int i = 0; i < 4; i++)
        t[ty + i * 8][tx] = W[(long long)(k0 + ty + i * 8) * EE + n0 + tx];
    __syncthreads();
#pragma unroll
    for (int i = 0; i < 4; i++)
        Wt[(long long)(n0 + ty + i * 8) * EE + k0 + tx] = __float2half_rn(t[tx][ty + i * 8]);
}

// ---------------------------------------------------------------------------
// fp16 tensor-core GEMM: C = A(MxK) @ Wt(NxK)^T + bias, fp32 accum/output.
// CTA tile 128x256, BK=32 halves, 256 threads (8 warps, each 64x64).
// mma.sync.m16n8k16.f32.f16.f16.f32; 3-stage cp.async pipeline, ONE barrier
// per chunk (wait_group -> sync -> issue next load -> mma).
// smask bit z: apply per-head row softmax (D=64) in the epilogue.
// ---------------------------------------------------------------------------
#define HP 80                     // bytes per smem row
#define ASTG (128*HP)             // 10240
#define BSTG (256*HP)             // 20480
#define STGH (ASTG+BSTG)          // 30720
#define GSMH (3*STGH)             // 92160
#define NCH 32                    // 1024/32 chunks

__device__ __forceinline__ void cp16(void* dst, const void* src) {
    unsigned d = (unsigned)__cvta_generic_to_shared(dst);
    asm volatile("cp.async.cg.shared.global [%0], [%1], 16;\n" :: "r"(d), "l"(src) : "memory");
}

__global__ __launch_bounds__(256, 1) void gemm_h(
    const __half* __restrict__ A,
    const __half* __restrict__ W0, const float* __restrict__ b0, float* __restrict__ C0,
    const __half* __restrict__ W1, const float* __restrict__ b1, float* __restrict__ C1,
    const __half* __restrict__ W2, const float* __restrict__ b2, float* __restrict__ C2,
    int smask)
{
    constexpr int K = EE;
    constexpr int N = EE;
    const __half* Wp = W0; const float* bp = b0; float* Cp = C0;
    if (blockIdx.z == 1) { Wp = W1; bp = b1; Cp = C1; }
    else if (blockIdx.z == 2) { Wp = W2; bp = b2; Cp = C2; }
    const bool do_sm = (smask >> blockIdx.z) & 1;

    extern __shared__ char smc[];

    const int tid = threadIdx.x;
    const int wid = tid >> 5;
    const int lane = tid & 31;
    const int g = lane >> 2;       // 0..7
    const int tg = lane & 3;       // 0..3
    const int wm = wid & 1;
    const int wn = wid >> 1;

    const long long brow = (long long)blockIdx.y * 128;
    const int bcol = blockIdx.x * 256;

    const __half* Abase = A + brow * K;
    const __half* Bbase = Wp + (long long)bcol * K;

    float acc[4][8][4];
#pragma unroll
    for (int mi = 0; mi < 4; mi++)
#pragma unroll
        for (int ni = 0; ni < 8; ni++)
#pragma unroll
            for (int r = 0; r < 4; r++) acc[mi][ni][r] = 0.0f;

    auto load_chunk = [&](int ch) {
        char* As = smc + (ch % 3) * STGH;
        char* Bs = As + ASTG;
        const __half* Ag = Abase + ch * 32;
        const __half* Bg = Bbase + ch * 32;
#pragma unroll
        for (int i = 0; i < 2; i++) {           // A: 128 rows x 4 granules
            int idx = tid + i * 256;
            int r = idx >> 2, c = idx & 3;
            cp16(As + r * HP + c * 16, Ag + (long long)r * K + c * 8);
        }
#pragma unroll
        for (int i = 0; i < 4; i++) {           // B: 256 rows x 4 granules
            int idx = tid + i * 256;
            int r = idx >> 2, c = idx & 3;
            cp16(Bs + r * HP + c * 16, Bg + (long long)r * K + c * 8);
        }
        asm volatile("cp.async.commit_group;\n" ::: "memory");
    };

    load_chunk(0);
    load_chunk(1);

    for (int c = 0; c < NCH; c++) {
        if (c + 1 < NCH) asm volatile("cp.async.wait_group 1;\n" ::: "memory");
        else             asm volatile("cp.async.wait_group 0;\n" ::: "memory");
        __syncthreads();
        // Safe to overwrite stage (c+2)%3 == (c-1)%3: the barrier above proves
        // every warp finished its mma reads of chunk c-1 (issued last iter).
        if (c + 2 < NCH) load_chunk(c + 2);

        const char* As = smc + (c % 3) * STGH;
        const char* Bs = As + ASTG;

#pragma unroll
        for (int s = 0; s < 2; s++) {           // two k16 steps per 32-half chunk
            unsigned af[4][4], bf[8][2];
            int kb = s * 32 + tg * 4;           // byte offset in row
#pragma unroll
            for (int mi = 0; mi < 4; mi++) {
                int m = wm * 64 + mi * 16 + g;
                af[mi][0] = *(const unsigned*)(As + m * HP + kb);
                af[mi][1] = *(const unsigned*)(As + (m + 8) * HP + kb);
                af[mi][2] = *(const unsigned*)(As + m * HP + kb + 16);
                af[mi][3] = *(const unsigned*)(As + (m + 8) * HP + kb + 16);
            }
#pragma unroll
            for (int ni = 0; ni < 8; ni++) {
                int n = wn * 64 + ni * 8 + g;
                bf[ni][0] = *(const unsigned*)(Bs + n * HP + kb);
                bf[ni][1] = *(const unsigned*)(Bs + n * HP + kb + 16);
            }
#pragma unroll
            for (int mi = 0; mi < 4; mi++)
#pragma unroll
                for (int ni = 0; ni < 8; ni++) {
                    asm volatile(
                        "mma.sync.aligned.m16n8k16.row.col.f32.f16.f16.f32 "
                        "{%0,%1,%2,%3}, {%4,%5,%6,%7}, {%8,%9}, {%0,%1,%2,%3};"
                        : "+f"(acc[mi][ni][0]), "+f"(acc[mi][ni][1]),
                          "+f"(acc[mi][ni][2]), "+f"(acc[mi][ni][3])
                        : "r"(af[mi][0]), "r"(af[mi][1]), "r"(af[mi][2]), "r"(af[mi][3]),
                          "r"(bf[ni][0]), "r"(bf[ni][1]));
                }
        }
    }

    // ---- epilogue: bias (+ optional per-head row softmax), write fp32 ----
    float2 bi[8];
#pragma unroll
    for (int ni = 0; ni < 8; ni++)
        bi[ni] = *(const float2*)(bp + bcol + wn * 64 + ni * 8 + 2 * tg);
#pragma unroll
    for (int mi = 0; mi < 4; mi++)
#pragma unroll
        for (int ni = 0; ni < 8; ni++) {
            acc[mi][ni][0] += bi[ni].x; acc[mi][ni][1] += bi[ni].y;
            acc[mi][ni][2] += bi[ni].x; acc[mi][ni][3] += bi[ni].y;
        }

    if (do_sm) {
        // Row softmax over the warp's 64 cols (= one head). Row owned by the
        // lane-quad g*4+{0..3}; shfl_xor 1,2 stay inside the quad.
#pragma unroll
        for (int mi = 0; mi < 4; mi++)
#pragma unroll
            for (int hf = 0; hf < 2; hf++) {
                float mx = -1e30f;
#pragma unroll
                for (int ni = 0; ni < 8; ni++)
                    mx = fmaxf(mx, fmaxf(acc[mi][ni][hf * 2], acc[mi][ni][hf * 2 + 1]));
                mx = fmaxf(mx, __shfl_xor_sync(0xFFFFFFFFu, mx, 1));
                mx = fmaxf(mx, __shfl_xor_sync(0xFFFFFFFFu, mx, 2));
                float sum = 0.0f;
#pragma unroll
                for (int ni = 0; ni < 8; ni++) {
                    float e0 = __expf(acc[mi][ni][hf * 2]     - mx);
                    float e1 = __expf(acc[mi][ni][hf * 2 + 1] - mx);
                    acc[mi][ni][hf * 2] = e0; acc[mi][ni][hf * 2 + 1] = e1;
                    sum += e0 + e1;
                }
                sum += __shfl_xor_sync(0xFFFFFFFFu, sum, 1);
                sum += __shfl_xor_sync(0xFFFFFFFFu, sum, 2);
                float inv = 1.0f / sum;
#pragma unroll
                for (int ni = 0; ni < 8; ni++) {
                    acc[mi][ni][hf * 2] *= inv; acc[mi][ni][hf * 2 + 1] *= inv;
                }
            }
    }

#pragma unroll
    for (int ni = 0; ni < 8; ni++) {
        int col = bcol + wn * 64 + ni * 8 + 2 * tg;
#pragma unroll
        for (int mi = 0; mi < 4; mi++) {
            long long r0 = brow + wm * 64 + mi * 16 + g;
            *(float2*)(Cp + r0 * N + col)       = make_float2(acc[mi][ni][0], acc[mi][ni][1]);
            *(float2*)(Cp + (r0 + 8) * N + col) = make_float2(acc[mi][ni][2], acc[mi][ni][3]);
        }
    }
}

// ---------------------------------------------------------------------------
// Attention phase 1: partial kv (64x128) + ksum (2x64) per (pair, split).
// grid = 1024: blockIdx.x = pair*SPLITS + split; each split covers 256 rows.
// Round-10 proven shape: 256 threads, 4x8 register tile.
// ---------------------------------------------------------------------------
__global__ __launch_bounds__(256, 1) void attn_p1()
{
    __shared__ float k_s[64 * 64];
    __shared__ float v_s[64 * 64];
    __shared__ float sc_s[64][2];

    const int bx = blockIdx.x;
    const int pair = bx >> 3;
    const int sp = bx & (SPLITS - 1);
    const int b = pair >> 4;
    const int h = pair & 15;
    const int tid = threadIdx.x;
    const int tx = tid & 15;
    const int ty = tid >> 4;

    const float* kbase = g_k + ((long long)b * LL) * EE + h * DD;
    const float* vbase = g_v + ((long long)b * LL) * EE + h * DD;

    const float cidx = 1.5707963267948966f / (float)LL;

    float accp[4][8];
#pragma unroll
    for (int i = 0; i < 4; i++)
#pragma unroll
        for (int j = 0; j < 8; j++) accp[i][j] = 0.0f;
    float ks_sin = 0.0f, ks_cos = 0.0f;

    const int mh = (tx & 7) * 8;
    for (int c = 0; c < LL / SPLITS / 64; c++) {     // 4 chunks of 64 rows
        int l0 = sp * (LL / SPLITS) + c * 64;
        if (tid < 64) {
            float s, co;
            __sincosf(cidx * (float)(l0 + tid + 1), &s, &co);
            sc_s[tid][0] = s; sc_s[tid][1] = co;
        }
#pragma unroll
        for (int i = 0; i < 4; i++) {
            int idx = tid + i * 256;
            int r  = idx >> 4;
            int c4 = idx & 15;
            *(float4*)&k_s[r * 64 + c4 * 4] = *(const float4*)(kbase + (long long)(l0 + r) * EE + c4 * 4);
            *(float4*)&v_s[r * 64 + c4 * 4] = *(const float4*)(vbase + (long long)(l0 + r) * EE + c4 * 4);
        }
        __syncthreads();
#pragma unroll 4
        for (int l = 0; l < 64; l++) {
            float f = sc_s[l][(tx < 8) ? 0 : 1];
            float ra[4], rv[8];
            *(float4*)&ra[0] = *(const float4*)&k_s[l * 64 + ty * 4];
            *(float4*)&rv[0] = *(const float4*)&v_s[l * 64 + mh];
            *(float4*)&rv[4] = *(const float4*)&v_s[l * 64 + mh + 4];
#pragma unroll
            for (int i = 0; i < 4; i++) {
                float a = ra[i] * f;
#pragma unroll
                for (int j = 0; j < 8; j++)
                    accp[i][j] = fmaf(a, rv[j], accp[i][j]);
            }
        }
        if (tid < 64) {
            for (int l = 0; l < 64; l++) {
                float kd = k_s[l * 64 + tid];
                ks_sin = fmaf(kd, sc_s[l][0], ks_sin);
                ks_cos = fmaf(kd, sc_s[l][1], ks_cos);
            }
        }
        __syncthreads();
    }

    float* part = g_part + (long long)bx * PSTRIDE;
#pragma unroll
    for (int i = 0; i < 4; i++) {
        *(float4*)&part[(ty * 4 + i) * 128 + tx * 8]     = make_float4(accp[i][0], accp[i][1], accp[i][2], accp[i][3]);
        *(float4*)&part[(ty * 4 + i) * 128 + tx * 8 + 4] = make_float4(accp[i][4], accp[i][5], accp[i][6], accp[i][7]);
    }
    if (tid < 64) { part[8192 + tid] = ks_sin; part[8256 + tid] = ks_cos; }
}

// ---------------------------------------------------------------------------
// Attention phase 2: reduce SPLITS partials, then per-row outputs for one
// 128-row chunk. grid = 2048: blockIdx.x = pair*16 + chunk. fp16 out -> g_ah.
// ---------------------------------------------------------------------------
__global__ __launch_bounds__(256, 1) void attn_p2()
{
    extern __shared__ float sm[];
    __shared__ float ksum_s[2][64];
    __shared__ float vsum_s[128];
    __shared__ float S_s[2];

    const int bx = blockIdx.x;
    const int pair = bx >> 4;
    const int ch = bx & 15;
    const int b = pair >> 4;
    const int h = pair & 15;
    const int tid = threadIdx.x;
    const int tx = tid & 15;
    const int ty = tid >> 4;

    float* kv_s = sm;            // [64][128]
    float* q_s  = sm + 8192;     // [128][64]

    const float* pb = g_part + (long long)pair * SPLITS * PSTRIDE;

    // reduce kv partials (SPLITS-way)
    for (int t = tid; t < 2048; t += 256) {
        float4 o = make_float4(0.f, 0.f, 0.f, 0.f);
#pragma unroll
        for (int s = 0; s < SPLITS; s++) {
            float4 a = *(const float4*)(pb + (long long)s * PSTRIDE + t * 4);
            o.x += a.x; o.y += a.y; o.z += a.z; o.w += a.w;
        }
        *(float4*)&kv_s[t * 4] = o;
    }
    if (tid < 128) {
        float s = 0.0f;
#pragma unroll
        for (int sp = 0; sp < SPLITS; sp++)
            s += pb[(long long)sp * PSTRIDE + 8192 + tid];
        ksum_s[tid >> 6][tid & 63] = s;
    }
    __syncthreads();
    if (tid < 128) {
        float s = 0.0f;
        for (int d = 0; d < 64; d++) s += kv_s[d * 128 + tid];
        vsum_s[tid] = s;
    }
    if (tid < 2) {
        float s = 0.0f;
        for (int d = 0; d < 64; d++) s += ksum_s[tid][d];
        S_s[tid] = s;
    }

    // load q chunk
    const float* qbase = g_q + ((long long)b * LL) * EE + h * DD;
    const int l0 = ch * 128;
#pragma unroll
    for (int i = 0; i < 8; i++) {
        int idx = tid + i * 256;
        int r  = idx >> 4;
        int c4 = idx & 15;
        *(float4*)&q_s[r * 64 + c4 * 4] = *(const float4*)(qbase + (long long)(l0 + r) * EE + c4 * 4);
    }
    __syncthreads();

    const float S_sin = S_s[0], S_cos = S_s[1];
    const float cidx = 1.5707963267948966f / (float)LL;

    float ts[8][4], tc2[8][4], us[8], uc[8];
#pragma unroll
    for (int i = 0; i < 8; i++) {
        us[i] = 0.0f; uc[i] = 0.0f;
#pragma unroll
        for (int j = 0; j < 4; j++) { ts[i][j] = 0.0f; tc2[i][j] = 0.0f; }
    }

#pragma unroll 2
    for (int d = 0; d < 64; d++) {
        float rkvs[4], rkvc[4];
        *(float4*)&rkvs[0] = *(const float4*)&kv_s[d * 128 + tx * 4];
        *(float4*)&rkvc[0] = *(const float4*)&kv_s[d * 128 + 64 + tx * 4];
        float kss = ksum_s[0][d], ksc = ksum_s[1][d];
#pragma unroll
        for (int i = 0; i < 8; i++) {
            float qd = q_s[(ty * 8 + i) * 64 + d];
            us[i] = fmaf(qd, kss, us[i]);
            uc[i] = fmaf(qd, ksc, uc[i]);
#pragma unroll
            for (int j = 0; j < 4; j++) {
                ts[i][j]  = fmaf(qd, rkvs[j], ts[i][j]);
                tc2[i][j] = fmaf(qd, rkvc[j], tc2[i][j]);
            }
        }
    }

#pragma unroll
    for (int i = 0; i < 8; i++) {
        int l = l0 + ty * 8 + i;
        float s, co;
        __sincosf(cidx * (float)(l + 1), &s, &co);
        float den1 = fmaf(s, us[i], co * uc[i]);
        float z1 = 1.0f / fmaxf(den1, EPSF);
        float den2 = s * (62.0f * S_sin + us[i]) + co * (62.0f * S_cos + uc[i]);
        float z2 = 1.0f / fmaxf(den2, EPSF);
        float tmp[4];
#pragma unroll
        for (int j = 0; j < 4; j++) {
            int m = tx * 4 + j;
            float n1 = fmaf(s, ts[i][j], co * tc2[i][j]);
            float n2 = s * (62.0f * vsum_s[m] + ts[i][j]) + co * (62.0f * vsum_s[64 + m] + tc2[i][j]);
            tmp[j] = n1 * z1 + n2 * z2;
        }
        __half2 h01 = __floats2half2_rn(tmp[0], tmp[1]);
        __half2 h23 = __floats2half2_rn(tmp[2], tmp[3]);
        __half* op = g_ah + ((long long)l * BB + b) * EE + h * DD + tx * 4;
        uint2 pk;
        pk.x = *(unsigned*)&h01;
        pk.y = *(unsigned*)&h23;
        *(uint2*)op = pk;
    }
}

// ---------------------------------------------------------------------------
extern "C" void kernel_launch(void* const* d_in, const int* in_sizes, int n_in,
                              void* d_out, int out_size)
{
    (void)in_sizes; (void)n_in; (void)out_size;
    const float* X  = (const float*)d_in[0];
    const float* Wq = (const float*)d_in[1];
    const float* bq = (const float*)d_in[2];
    const float* Wk = (const float*)d_in[3];
    const float* bk = (const float*)d_in[4];
    const float* Wv = (const float*)d_in[5];
    const float* bv = (const float*)d_in[6];
    const float* Wo = (const float*)d_in[7];
    const float* bo = (const float*)d_in[8];
    float* out = (float*)d_out;

    float *gq, *gk, *gv;
    __half *gah, *gxh, *gwq, *gwk, *gwv, *gwo;
    cudaGetSymbolAddress((void**)&gq, g_q);
    cudaGetSymbolAddress((void**)&gk, g_k);
    cudaGetSymbolAddress((void**)&gv, g_v);
    cudaGetSymbolAddress((void**)&gah, g_ah);
    cudaGetSymbolAddress((void**)&gxh, g_xh);
    cudaGetSymbolAddress((void**)&gwq, g_wqh);
    cudaGetSymbolAddress((void**)&gwk, g_wkh);
    cudaGetSymbolAddress((void**)&gwv, g_wvh);
    cudaGetSymbolAddress((void**)&gwo, g_woh);

    cudaFuncSetAttribute(gemm_h, cudaFuncAttributeMaxDynamicSharedMemorySize, GSMH);
    cudaFuncSetAttribute(attn_p2, cudaFuncAttributeMaxDynamicSharedMemorySize, 65536);

    // 0) convert X and weights (transposed) to fp16
    conv_x<<<(int)(((long long)MROWS * EE / 8 + 255) / 256), 256>>>(X);
    wtrans_h<<<dim3(32, 32, 4), 256>>>(Wq, Wk, Wv, Wo);

    // 1) fused QKV projections with per-head softmax on q,k in the epilogue
    gemm_h<<<dim3(EE / 256, MROWS / 128, 3), 256, GSMH>>>(
        gxh, gwq, bq, gq, gwk, bk, gk, gwv, bv, gv, 0b011);

    // 2) linear attention: split phase 1 / phase 2 for occupancy
    attn_p1<<<128 * SPLITS, 256>>>();
    attn_p2<<<2048, 256, 65536>>>();

    // 3) output projection into d_out (fp16 tensor cores)
    gemm_h<<<dim3(EE / 256, MROWS / 128, 1), 256, GSMH>>>(
        gah, gwo, bo, out, gwo, bo, out, gwo, bo, out, 0);
}

// round 13
// speedup vs baseline: 1.7043x; 1.1243x over previous
#include <cuda_runtime.h>
#include <cuda_fp16.h>
#include <math.h>
#include <stdint.h>

// Problem constants
#define BB 8
#define LL 2048
#define EE 1024
#define HH 16
#define DD 64
#define MROWS (BB*LL)          // 16384
#define EPSF 1e-6f

// Scratch (device globals: allocation-free rule)
__device__ float  g_q[(size_t)MROWS * EE];
__device__ float  g_k[(size_t)MROWS * EE];
__device__ float  g_v[(size_t)MROWS * EE];
__device__ __half g_ah[(size_t)MROWS * EE];      // fp16 attention output (Wo GEMM input)
__device__ __half g_xh[(size_t)MROWS * EE];      // fp16 X
__device__ __half g_wqh[(size_t)EE * EE];        // fp16 transposed weights [N][K]
__device__ __half g_wkh[(size_t)EE * EE];
__device__ __half g_wvh[(size_t)EE * EE];
__device__ __half g_woh[(size_t)EE * EE];
#define SPLITS 8
#define PSTRIDE 8320                              // 64*128 kv + 2*64 ksum
__device__ float  g_part[(size_t)128 * SPLITS * PSTRIDE];   // attn phase-1 partials

__device__ __forceinline__ unsigned tf32u(float x) {
    unsigned u;
    asm("cvt.rna.tf32.f32 %0, %1;" : "=r"(u) : "f"(x));
    return u;
}

// ---------------------------------------------------------------------------
// Conversions
// ---------------------------------------------------------------------------
__global__ __launch_bounds__(256) void conv_x(const float* __restrict__ X)
{
    long long i8 = (long long)blockIdx.x * 256 + threadIdx.x;   // 8 floats each
    long long base = i8 * 8;
    if (base >= (long long)MROWS * EE) return;
    float4 v0 = *(const float4*)(X + base);
    float4 v1 = *(const float4*)(X + base + 4);
    __half2 h[4];
    h[0] = __floats2half2_rn(v0.x, v0.y);
    h[1] = __floats2half2_rn(v0.z, v0.w);
    h[2] = __floats2half2_rn(v1.x, v1.y);
    h[3] = __floats2half2_rn(v1.z, v1.w);
    *(uint4*)(g_xh + base) = *(uint4*)h;
}

// Weight transpose + fp16 round: Wt[n][k] = rn(W[k][n]). 32x32 tiles.
__global__ __launch_bounds__(256) void wtrans_h(
    const float* __restrict__ Wq, const float* __restrict__ Wk,
    const float* __restrict__ Wv, const float* __restrict__ Wo)
{
    __shared__ float t[32][33];
    const float* W; __half* Wt;
    switch (blockIdx.z) {
        case 0: W = Wq; Wt = g_wqh; break;
        case 1: W = Wk; Wt = g_wkh; break;
        case 2: W = Wv; Wt = g_wvh; break;
        default: W = Wo; Wt = g_woh; break;
    }
    int tx = threadIdx.x & 31, ty = threadIdx.x >> 5;   // 32 x 8
    int k0 = blockIdx.y * 32, n0 = blockIdx.x * 32;
#pragma unroll
    for (int i = 0; i < 4; i++)
        t[ty + i * 8][tx] = W[(long long)(k0 + ty + i * 8) * EE + n0 + tx];
    __syncthreads();
#pragma unroll
    for (int i = 0; i < 4; i++)
        Wt[(long long)(n0 + ty + i * 8) * EE + k0 + tx] = __float2half_rn(t[tx][ty + i * 8]);
}

// ---------------------------------------------------------------------------
// fp16 tensor-core GEMM: C = A(MxK) @ Wt(NxK)^T + bias, fp32 accum/output.
// CTA tile 128x256, BK=32 halves, 256 threads (8 warps, each 64x64).
// mma.sync.m16n8k16.f32.f16.f16.f32; 3-stage cp.async pipeline, ONE barrier
// per chunk. smask bit z: per-head row softmax (D=64) in the epilogue.
// ---------------------------------------------------------------------------
#define HP 80                     // bytes per smem row
#define ASTG (128*HP)             // 10240
#define BSTG (256*HP)             // 20480
#define STGH (ASTG+BSTG)          // 30720
#define GSMH (3*STGH)             // 92160
#define NCH 32                    // 1024/32 chunks

__device__ __forceinline__ void cp16(void* dst, const void* src) {
    unsigned d = (unsigned)__cvta_generic_to_shared(dst);
    asm volatile("cp.async.cg.shared.global [%0], [%1], 16;\n" :: "r"(d), "l"(src) : "memory");
}

__global__ __launch_bounds__(256, 1) void gemm_h(
    const __half* __restrict__ A,
    const __half* __restrict__ W0, const float* __restrict__ b0, float* __restrict__ C0,
    const __half* __restrict__ W1, const float* __restrict__ b1, float* __restrict__ C1,
    const __half* __restrict__ W2, const float* __restrict__ b2, float* __restrict__ C2,
    int smask)
{
    constexpr int K = EE;
    constexpr int N = EE;
    const __half* Wp = W0; const float* bp = b0; float* Cp = C0;
    if (blockIdx.z == 1) { Wp = W1; bp = b1; Cp = C1; }
    else if (blockIdx.z == 2) { Wp = W2; bp = b2; Cp = C2; }
    const bool do_sm = (smask >> blockIdx.z) & 1;

    extern __shared__ char smc[];

    const int tid = threadIdx.x;
    const int wid = tid >> 5;
    const int lane = tid & 31;
    const int g = lane >> 2;       // 0..7
    const int tg = lane & 3;       // 0..3
    const int wm = wid & 1;
    const int wn = wid >> 1;

    const long long brow = (long long)blockIdx.y * 128;
    const int bcol = blockIdx.x * 256;

    const __half* Abase = A + brow * K;
    const __half* Bbase = Wp + (long long)bcol * K;

    float acc[4][8][4];
#pragma unroll
    for (int mi = 0; mi < 4; mi++)
#pragma unroll
        for (int ni = 0; ni < 8; ni++)
#pragma unroll
            for (int r = 0; r < 4; r++) acc[mi][ni][r] = 0.0f;

    auto load_chunk = [&](int ch) {
        char* As = smc + (ch % 3) * STGH;
        char* Bs = As + ASTG;
        const __half* Ag = Abase + ch * 32;
        const __half* Bg = Bbase + ch * 32;
#pragma unroll
        for (int i = 0; i < 2; i++) {           // A: 128 rows x 4 granules
            int idx = tid + i * 256;
            int r = idx >> 2, c = idx & 3;
            cp16(As + r * HP + c * 16, Ag + (long long)r * K + c * 8);
        }
#pragma unroll
        for (int i = 0; i < 4; i++) {           // B: 256 rows x 4 granules
            int idx = tid + i * 256;
            int r = idx >> 2, c = idx & 3;
            cp16(Bs + r * HP + c * 16, Bg + (long long)r * K + c * 8);
        }
        asm volatile("cp.async.commit_group;\n" ::: "memory");
    };

    load_chunk(0);
    load_chunk(1);

    for (int c = 0; c < NCH; c++) {
        if (c + 1 < NCH) asm volatile("cp.async.wait_group 1;\n" ::: "memory");
        else             asm volatile("cp.async.wait_group 0;\n" ::: "memory");
        __syncthreads();
        // Safe to overwrite stage (c+2)%3 == (c-1)%3: the barrier above proves
        // every warp finished its mma reads of chunk c-1 (issued last iter).
        if (c + 2 < NCH) load_chunk(c + 2);

        const char* As = smc + (c % 3) * STGH;
        const char* Bs = As + ASTG;

#pragma unroll
        for (int s = 0; s < 2; s++) {           // two k16 steps per 32-half chunk
            unsigned af[4][4], bf[8][2];
            int kb = s * 32 + tg * 4;           // byte offset in row
#pragma unroll
            for (int mi = 0; mi < 4; mi++) {
                int m = wm * 64 + mi * 16 + g;
                af[mi][0] = *(const unsigned*)(As + m * HP + kb);
                af[mi][1] = *(const unsigned*)(As + (m + 8) * HP + kb);
                af[mi][2] = *(const unsigned*)(As + m * HP + kb + 16);
                af[mi][3] = *(const unsigned*)(As + (m + 8) * HP + kb + 16);
            }
#pragma unroll
            for (int ni = 0; ni < 8; ni++) {
                int n = wn * 64 + ni * 8 + g;
                bf[ni][0] = *(const unsigned*)(Bs + n * HP + kb);
                bf[ni][1] = *(const unsigned*)(Bs + n * HP + kb + 16);
            }
#pragma unroll
            for (int mi = 0; mi < 4; mi++)
#pragma unroll
                for (int ni = 0; ni < 8; ni++) {
                    asm volatile(
                        "mma.sync.aligned.m16n8k16.row.col.f32.f16.f16.f32 "
                        "{%0,%1,%2,%3}, {%4,%5,%6,%7}, {%8,%9}, {%0,%1,%2,%3};"
                        : "+f"(acc[mi][ni][0]), "+f"(acc[mi][ni][1]),
                          "+f"(acc[mi][ni][2]), "+f"(acc[mi][ni][3])
                        : "r"(af[mi][0]), "r"(af[mi][1]), "r"(af[mi][2]), "r"(af[mi][3]),
                          "r"(bf[ni][0]), "r"(bf[ni][1]));
                }
        }
    }

    // ---- epilogue: bias (+ optional per-head row softmax), write fp32 ----
    float2 bi[8];
#pragma unroll
    for (int ni = 0; ni < 8; ni++)
        bi[ni] = *(const float2*)(bp + bcol + wn * 64 + ni * 8 + 2 * tg);
#pragma unroll
    for (int mi = 0; mi < 4; mi++)
#pragma unroll
        for (int ni = 0; ni < 8; ni++) {
            acc[mi][ni][0] += bi[ni].x; acc[mi][ni][1] += bi[ni].y;
            acc[mi][ni][2] += bi[ni].x; acc[mi][ni][3] += bi[ni].y;
        }

    if (do_sm) {
        // Row softmax over the warp's 64 cols (= one head). Row owned by the
        // lane-quad g*4+{0..3}; shfl_xor 1,2 stay inside the quad.
#pragma unroll
        for (int mi = 0; mi < 4; mi++)
#pragma unroll
            for (int hf = 0; hf < 2; hf++) {
                float mx = -1e30f;
#pragma unroll
                for (int ni = 0; ni < 8; ni++)
                    mx = fmaxf(mx, fmaxf(acc[mi][ni][hf * 2], acc[mi][ni][hf * 2 + 1]));
                mx = fmaxf(mx, __shfl_xor_sync(0xFFFFFFFFu, mx, 1));
                mx = fmaxf(mx, __shfl_xor_sync(0xFFFFFFFFu, mx, 2));
                float sum = 0.0f;
#pragma unroll
                for (int ni = 0; ni < 8; ni++) {
                    float e0 = __expf(acc[mi][ni][hf * 2]     - mx);
                    float e1 = __expf(acc[mi][ni][hf * 2 + 1] - mx);
                    acc[mi][ni][hf * 2] = e0; acc[mi][ni][hf * 2 + 1] = e1;
                    sum += e0 + e1;
                }
                sum += __shfl_xor_sync(0xFFFFFFFFu, sum, 1);
                sum += __shfl_xor_sync(0xFFFFFFFFu, sum, 2);
                float inv = 1.0f / sum;
#pragma unroll
                for (int ni = 0; ni < 8; ni++) {
                    acc[mi][ni][hf * 2] *= inv; acc[mi][ni][hf * 2 + 1] *= inv;
                }
            }
    }

#pragma unroll
    for (int ni = 0; ni < 8; ni++) {
        int col = bcol + wn * 64 + ni * 8 + 2 * tg;
#pragma unroll
        for (int mi = 0; mi < 4; mi++) {
            long long r0 = brow + wm * 64 + mi * 16 + g;
            *(float2*)(Cp + r0 * N + col)       = make_float2(acc[mi][ni][0], acc[mi][ni][1]);
            *(float2*)(Cp + (r0 + 8) * N + col) = make_float2(acc[mi][ni][2], acc[mi][ni][3]);
        }
    }
}

// ---------------------------------------------------------------------------
// Attention phase 1 (tensor cores, tf32): partial kv + ksum per (pair, split).
// grid = 1024: blockIdx.x = pair*SPLITS + split; each split covers 256 rows.
// D[128 features][64 vcols] += A(features x l) @ B(l x vcols) via
// mma.sync.m16n8k8.tf32. A elements built on the fly: k_s[l][d] * trig[l]
// (transpose free at LDS time: tf32 fragments are independent scalars).
// Smem row stride 72 floats -> all fragment LDS hit 32 distinct banks.
// Warp w owns 16 features (m0 = w*16), all 64 cols; 8 warps = 128 features.
// ---------------------------------------------------------------------------
#define KST 72

__global__ __launch_bounds__(256, 1) void attn_p1()
{
    __shared__ float k_s[64 * KST];
    __shared__ float v_s[64 * KST];
    __shared__ float sc_s[64][2];

    const int bx = blockIdx.x;
    const int pair = bx >> 3;
    const int sp = bx & (SPLITS - 1);
    const int b = pair >> 4;
    const int h = pair & 15;
    const int tid = threadIdx.x;
    const int wid = tid >> 5;
    const int lane = tid & 31;
    const int g = lane >> 2;          // 0..7
    const int tg = lane & 3;          // 0..3

    const int m0 = wid * 16;          // feature band base
    const int selA = m0 >> 6;         // 0 = sin, 1 = cos (constant per warp)
    const int dlo = (m0 & 63) + g;    // k dim for rows g, g+8 of the band
    const int dhi = dlo + 8;

    const float* kbase = g_k + ((long long)b * LL) * EE + h * DD;
    const float* vbase = g_v + ((long long)b * LL) * EE + h * DD;

    const float cidx = 1.5707963267948966f / (float)LL;

    float acc[8][4];
#pragma unroll
    for (int ni = 0; ni < 8; ni++)
#pragma unroll
        for (int r = 0; r < 4; r++) acc[ni][r] = 0.0f;
    float ks_sin = 0.0f, ks_cos = 0.0f;

    for (int c = 0; c < LL / SPLITS / 64; c++) {     // 4 chunks of 64 rows
        int l0 = sp * (LL / SPLITS) + c * 64;
        if (tid < 64) {
            float s, co;
            __sincosf(cidx * (float)(l0 + tid + 1), &s, &co);
            sc_s[tid][0] = s; sc_s[tid][1] = co;
        }
#pragma unroll
        for (int i = 0; i < 4; i++) {
            int idx = tid + i * 256;
            int r  = idx >> 4;        // 0..63
            int c4 = idx & 15;
            *(float4*)&k_s[r * KST + c4 * 4] = *(const float4*)(kbase + (long long)(l0 + r) * EE + c4 * 4);
            *(float4*)&v_s[r * KST + c4 * 4] = *(const float4*)(vbase + (long long)(l0 + r) * EE + c4 * 4);
        }
        __syncthreads();

#pragma unroll
        for (int ks = 0; ks < 8; ks++) {
            const int la = ks * 8 + tg;       // k index tg, tg+4 rows
            const float t0 = sc_s[la][selA];
            const float t1 = sc_s[la + 4][selA];
            unsigned a0 = tf32u(k_s[la * KST + dlo] * t0);
            unsigned a1 = tf32u(k_s[la * KST + dhi] * t0);
            unsigned a2 = tf32u(k_s[(la + 4) * KST + dlo] * t1);
            unsigned a3 = tf32u(k_s[(la + 4) * KST + dhi] * t1);
#pragma unroll
            for (int ni = 0; ni < 8; ni++) {
                unsigned b0 = tf32u(v_s[la * KST + ni * 8 + g]);
                unsigned b1 = tf32u(v_s[(la + 4) * KST + ni * 8 + g]);
                asm volatile(
                    "mma.sync.aligned.m16n8k8.row.col.f32.tf32.tf32.f32 "
                    "{%0,%1,%2,%3}, {%4,%5,%6,%7}, {%8,%9}, {%0,%1,%2,%3};"
                    : "+f"(acc[ni][0]), "+f"(acc[ni][1]),
                      "+f"(acc[ni][2]), "+f"(acc[ni][3])
                    : "r"(a0), "r"(a1), "r"(a2), "r"(a3), "r"(b0), "r"(b1));
            }
        }

        if (tid < 64) {
            for (int l = 0; l < 64; l++) {
                float kd = k_s[l * KST + tid];
                ks_sin = fmaf(kd, sc_s[l][0], ks_sin);
                ks_cos = fmaf(kd, sc_s[l][1], ks_cos);
            }
        }
        __syncthreads();
    }

    // epilogue: map fragments into part[d][sel*64 + n] (layout p2 expects)
    float* part = g_part + (long long)bx * PSTRIDE;
    const int d1 = (m0 & 63) + g;          // feature row m0+g
    const int d2 = d1 + 8;                 // feature row m0+g+8
#pragma unroll
    for (int ni = 0; ni < 8; ni++) {
        int n = ni * 8 + 2 * tg;
        *(float2*)&part[d1 * 128 + selA * 64 + n] = make_float2(acc[ni][0], acc[ni][1]);
        *(float2*)&part[d2 * 128 + selA * 64 + n] = make_float2(acc[ni][2], acc[ni][3]);
    }
    if (tid < 64) { part[8192 + tid] = ks_sin; part[8256 + tid] = ks_cos; }
}

// ---------------------------------------------------------------------------
// Attention phase 2: reduce SPLITS partials, then per-row outputs for one
// 128-row chunk. grid = 2048: blockIdx.x = pair*16 + chunk. fp16 out -> g_ah.
// ---------------------------------------------------------------------------
__global__ __launch_bounds__(256, 1) void attn_p2()
{
    extern __shared__ float sm[];
    __shared__ float ksum_s[2][64];
    __shared__ float vsum_s[128];
    __shared__ float S_s[2];

    const int bx = blockIdx.x;
    const int pair = bx >> 4;
    const int ch = bx & 15;
    const int b = pair >> 4;
    const int h = pair & 15;
    const int tid = threadIdx.x;
    const int tx = tid & 15;
    const int ty = tid >> 4;

    float* kv_s = sm;            // [64][128]
    float* q_s  = sm + 8192;     // [128][64]

    const float* pb = g_part + (long long)pair * SPLITS * PSTRIDE;

    // reduce kv partials (SPLITS-way)
    for (int t = tid; t < 2048; t += 256) {
        float4 o = make_float4(0.f, 0.f, 0.f, 0.f);
#pragma unroll
        for (int s = 0; s < SPLITS; s++) {
            float4 a = *(const float4*)(pb + (long long)s * PSTRIDE + t * 4);
            o.x += a.x; o.y += a.y; o.z += a.z; o.w += a.w;
        }
        *(float4*)&kv_s[t * 4] = o;
    }
    if (tid < 128) {
        float s = 0.0f;
#pragma unroll
        for (int sp = 0; sp < SPLITS; sp++)
            s += pb[(long long)sp * PSTRIDE + 8192 + tid];
        ksum_s[tid >> 6][tid & 63] = s;
    }
    __syncthreads();
    if (tid < 128) {
        float s = 0.0f;
        for (int d = 0; d < 64; d++) s += kv_s[d * 128 + tid];
        vsum_s[tid] = s;
    }
    if (tid < 2) {
        float s = 0.0f;
        for (int d = 0; d < 64; d++) s += ksum_s[tid][d];
        S_s[tid] = s;
    }

    // load q chunk
    const float* qbase = g_q + ((long long)b * LL) * EE + h * DD;
    const int l0 = ch * 128;
#pragma unroll
    for (int i = 0; i < 8; i++) {
        int idx = tid + i * 256;
        int r  = idx >> 4;
        int c4 = idx & 15;
        *(float4*)&q_s[r * 64 + c4 * 4] = *(const float4*)(qbase + (long long)(l0 + r) * EE + c4 * 4);
    }
    __syncthreads();

    const float S_sin = S_s[0], S_cos = S_s[1];
    const float cidx = 1.5707963267948966f / (float)LL;

    float ts[8][4], tc2[8][4], us[8], uc[8];
#pragma unroll
    for (int i = 0; i < 8; i++) {
        us[i] = 0.0f; uc[i] = 0.0f;
#pragma unroll
        for (int j = 0; j < 4; j++) { ts[i][j] = 0.0f; tc2[i][j] = 0.0f; }
    }

#pragma unroll 2
    for (int d = 0; d < 64; d++) {
        float rkvs[4], rkvc[4];
        *(float4*)&rkvs[0] = *(const float4*)&kv_s[d * 128 + tx * 4];
        *(float4*)&rkvc[0] = *(const float4*)&kv_s[d * 128 + 64 + tx * 4];
        float kss = ksum_s[0][d], ksc = ksum_s[1][d];
#pragma unroll
        for (int i = 0; i < 8; i++) {
            float qd = q_s[(ty * 8 + i) * 64 + d];
            us[i] = fmaf(qd, kss, us[i]);
            uc[i] = fmaf(qd, ksc, uc[i]);
#pragma unroll
            for (int j = 0; j < 4; j++) {
                ts[i][j]  = fmaf(qd, rkvs[j], ts[i][j]);
                tc2[i][j] = fmaf(qd, rkvc[j], tc2[i][j]);
            }
        }
    }

#pragma unroll
    for (int i = 0; i < 8; i++) {
        int l = l0 + ty * 8 + i;
        float s, co;
        __sincosf(cidx * (float)(l + 1), &s, &co);
        float den1 = fmaf(s, us[i], co * uc[i]);
        float z1 = 1.0f / fmaxf(den1, EPSF);
        float den2 = s * (62.0f * S_sin + us[i]) + co * (62.0f * S_cos + uc[i]);
        float z2 = 1.0f / fmaxf(den2, EPSF);
        float tmp[4];
#pragma unroll
        for (int j = 0; j < 4; j++) {
            int m = tx * 4 + j;
            float n1 = fmaf(s, ts[i][j], co * tc2[i][j]);
            float n2 = s * (62.0f * vsum_s[m] + ts[i][j]) + co * (62.0f * vsum_s[64 + m] + tc2[i][j]);
            tmp[j] = n1 * z1 + n2 * z2;
        }
        __half2 h01 = __floats2half2_rn(tmp[0], tmp[1]);
        __half2 h23 = __floats2half2_rn(tmp[2], tmp[3]);
        __half* op = g_ah + ((long long)l * BB + b) * EE + h * DD + tx * 4;
        uint2 pk;
        pk.x = *(unsigned*)&h01;
        pk.y = *(unsigned*)&h23;
        *(uint2*)op = pk;
    }
}

// ---------------------------------------------------------------------------
extern "C" void kernel_launch(void* const* d_in, const int* in_sizes, int n_in,
                              void* d_out, int out_size)
{
    (void)in_sizes; (void)n_in; (void)out_size;
    const float* X  = (const float*)d_in[0];
    const float* Wq = (const float*)d_in[1];
    const float* bq = (const float*)d_in[2];
    const float* Wk = (const float*)d_in[3];
    const float* bk = (const float*)d_in[4];
    const float* Wv = (const float*)d_in[5];
    const float* bv = (const float*)d_in[6];
    const float* Wo = (const float*)d_in[7];
    const float* bo = (const float*)d_in[8];
    float* out = (float*)d_out;

    float *gq, *gk, *gv;
    __half *gah, *gxh, *gwq, *gwk, *gwv, *gwo;
    cudaGetSymbolAddress((void**)&gq, g_q);
    cudaGetSymbolAddress((void**)&gk, g_k);
    cudaGetSymbolAddress((void**)&gv, g_v);
    cudaGetSymbolAddress((void**)&gah, g_ah);
    cudaGetSymbolAddress((void**)&gxh, g_xh);
    cudaGetSymbolAddress((void**)&gwq, g_wqh);
    cudaGetSymbolAddress((void**)&gwk, g_wkh);
    cudaGetSymbolAddress((void**)&gwv, g_wvh);
    cudaGetSymbolAddress((void**)&gwo, g_woh);

    cudaFuncSetAttribute(gemm_h, cudaFuncAttributeMaxDynamicSharedMemorySize, GSMH);
    cudaFuncSetAttribute(attn_p2, cudaFuncAttributeMaxDynamicSharedMemorySize, 65536);

    // 0) convert X and weights (transposed) to fp16
    conv_x<<<(int)(((long long)MROWS * EE / 8 + 255) / 256), 256>>>(X);
    wtrans_h<<<dim3(32, 32, 4), 256>>>(Wq, Wk, Wv, Wo);

    // 1) fused QKV projections with per-head softmax on q,k in the epilogue
    gemm_h<<<dim3(EE / 256, MROWS / 128, 3), 256, GSMH>>>(
        gxh, gwq, bq, gq, gwk, bk, gk, gwv, bv, gv, 0b011);

    // 2) linear attention: split phase 1 / phase 2 for occupancy
    attn_p1<<<128 * SPLITS, 256>>>();
    attn_p2<<<2048, 256, 65536>>>();

    // 3) output projection into d_out (fp16 tensor cores)
    gemm_h<<<dim3(EE / 256, MROWS / 128, 1), 256, GSMH>>>(
        gah, gwo, bo, out, gwo, bo, out, gwo, bo, out, 0);
}

// round 15
// speedup vs baseline: 1.8979x; 1.1135x over previous
#include <cuda_runtime.h>
#include <cuda_fp16.h>
#include <math.h>
#include <stdint.h>

// Problem constants
#define BB 8
#define LL 2048
#define EE 1024
#define HH 16
#define DD 64
#define MROWS (BB*LL)          // 16384
#define EPSF 1e-6f

// Scratch (device globals: allocation-free rule)
__device__ float  g_q[(size_t)MROWS * EE];
__device__ float  g_k[(size_t)MROWS * EE];
__device__ float  g_v[(size_t)MROWS * EE];
__device__ __half g_ah[(size_t)MROWS * EE];      // fp16 attention output (Wo GEMM input)
__device__ __half g_xh[(size_t)MROWS * EE];      // fp16 X
__device__ __half g_wqh[(size_t)EE * EE];        // fp16 transposed weights [N][K]
__device__ __half g_wkh[(size_t)EE * EE];
__device__ __half g_wvh[(size_t)EE * EE];
__device__ __half g_woh[(size_t)EE * EE];
#define SPLITS 8
#define PSTRIDE 8320                              // 64*128 kv + 2*64 ksum
__device__ float  g_part[(size_t)128 * SPLITS * PSTRIDE];   // attn phase-1 partials

__device__ __forceinline__ unsigned tf32u(float x) {
    unsigned u;
    asm("cvt.rna.tf32.f32 %0, %1;" : "=r"(u) : "f"(x));
    return u;
}
__device__ __forceinline__ float tf32f(float x) {
    return __uint_as_float(tf32u(x));
}

// ---------------------------------------------------------------------------
// Conversions
// ---------------------------------------------------------------------------
__global__ __launch_bounds__(256) void conv_x(const float* __restrict__ X)
{
    long long i8 = (long long)blockIdx.x * 256 + threadIdx.x;   // 8 floats each
    long long base = i8 * 8;
    if (base >= (long long)MROWS * EE) return;
    float4 v0 = *(const float4*)(X + base);
    float4 v1 = *(const float4*)(X + base + 4);
    __half2 h[4];
    h[0] = __floats2half2_rn(v0.x, v0.y);
    h[1] = __floats2half2_rn(v0.z, v0.w);
    h[2] = __floats2half2_rn(v1.x, v1.y);
    h[3] = __floats2half2_rn(v1.z, v1.w);
    *(uint4*)(g_xh + base) = *(uint4*)h;
}

// Weight transpose + fp16 round: Wt[n][k] = rn(W[k][n]). 32x32 tiles.
__global__ __launch_bounds__(256) void wtrans_h(
    const float* __restrict__ Wq, const float* __restrict__ Wk,
    const float* __restrict__ Wv, const float* __restrict__ Wo)
{
    __shared__ float t[32][33];
    const float* W; __half* Wt;
    switch (blockIdx.z) {
        case 0: W = Wq; Wt = g_wqh; break;
        case 1: W = Wk; Wt = g_wkh; break;
        case 2: W = Wv; Wt = g_wvh; break;
        default: W = Wo; Wt = g_woh; break;
    }
    int tx = threadIdx.x & 31, ty = threadIdx.x >> 5;   // 32 x 8
    int k0 = blockIdx.y * 32, n0 = blockIdx.x * 32;
#pragma unroll
    for (int i = 0; i < 4; i++)
        t[ty + i * 8][tx] = W[(long long)(k0 + ty + i * 8) * EE + n0 + tx];
    __syncthreads();
#pragma unroll
    for (int i = 0; i < 4; i++)
        Wt[(long long)(n0 + ty + i * 8) * EE + k0 + tx] = __float2half_rn(t[tx][ty + i * 8]);
}

// ---------------------------------------------------------------------------
// fp16 tensor-core GEMM: C = A(MxK) @ Wt(NxK)^T + bias, fp32 accum/output.
// CTA tile 128x256, BK=32 halves, 256 threads (8 warps, each 64x64).
// mma.sync.m16n8k16.f32.f16.f16.f32; 3-stage cp.async pipeline, ONE barrier
// per chunk. smask bit z: per-head row softmax (D=64) in the epilogue.
// ---------------------------------------------------------------------------
#define HP 80                     // bytes per smem row
#define ASTG (128*HP)             // 10240
#define BSTG (256*HP)             // 20480
#define STGH (ASTG+BSTG)          // 30720
#define GSMH (3*STGH)             // 92160
#define NCH 32                    // 1024/32 chunks

__device__ __forceinline__ void cp16(void* dst, const void* src) {
    unsigned d = (unsigned)__cvta_generic_to_shared(dst);
    asm volatile("cp.async.cg.shared.global [%0], [%1], 16;\n" :: "r"(d), "l"(src) : "memory");
}

__global__ __launch_bounds__(256, 1) void gemm_h(
    const __half* __restrict__ A,
    const __half* __restrict__ W0, const float* __restrict__ b0, float* __restrict__ C0,
    const __half* __restrict__ W1, const float* __restrict__ b1, float* __restrict__ C1,
    const __half* __restrict__ W2, const float* __restrict__ b2, float* __restrict__ C2,
    int smask)
{
    constexpr int K = EE;
    constexpr int N = EE;
    const __half* Wp = W0; const float* bp = b0; float* Cp = C0;
    if (blockIdx.z == 1) { Wp = W1; bp = b1; Cp = C1; }
    else if (blockIdx.z == 2) { Wp = W2; bp = b2; Cp = C2; }
    const bool do_sm = (smask >> blockIdx.z) & 1;

    extern __shared__ char smc[];

    const int tid = threadIdx.x;
    const int wid = tid >> 5;
    const int lane = tid & 31;
    const int g = lane >> 2;       // 0..7
    const int tg = lane & 3;       // 0..3
    const int wm = wid & 1;
    const int wn = wid >> 1;

    const long long brow = (long long)blockIdx.y * 128;
    const int bcol = blockIdx.x * 256;

    const __half* Abase = A + brow * K;
    const __half* Bbase = Wp + (long long)bcol * K;

    float acc[4][8][4];
#pragma unroll
    for (int mi = 0; mi < 4; mi++)
#pragma unroll
        for (int ni = 0; ni < 8; ni++)
#pragma unroll
            for (int r = 0; r < 4; r++) acc[mi][ni][r] = 0.0f;

    auto load_chunk = [&](int ch) {
        char* As = smc + (ch % 3) * STGH;
        char* Bs = As + ASTG;
        const __half* Ag = Abase + ch * 32;
        const __half* Bg = Bbase + ch * 32;
#pragma unroll
        for (int i = 0; i < 2; i++) {           // A: 128 rows x 4 granules
            int idx = tid + i * 256;
            int r = idx >> 2, c = idx & 3;
            cp16(As + r * HP + c * 16, Ag + (long long)r * K + c * 8);
        }
#pragma unroll
        for (int i = 0; i < 4; i++) {           // B: 256 rows x 4 granules
            int idx = tid + i * 256;
            int r = idx >> 2, c = idx & 3;
            cp16(Bs + r * HP + c * 16, Bg + (long long)r * K + c * 8);
        }
        asm volatile("cp.async.commit_group;\n" ::: "memory");
    };

    load_chunk(0);
    load_chunk(1);

    for (int c = 0; c < NCH; c++) {
        if (c + 1 < NCH) asm volatile("cp.async.wait_group 1;\n" ::: "memory");
        else             asm volatile("cp.async.wait_group 0;\n" ::: "memory");
        __syncthreads();
        // Safe to overwrite stage (c+2)%3 == (c-1)%3: the barrier above proves
        // every warp finished its mma reads of chunk c-1 (issued last iter).
        if (c + 2 < NCH) load_chunk(c + 2);

        const char* As = smc + (c % 3) * STGH;
        const char* Bs = As + ASTG;

#pragma unroll
        for (int s = 0; s < 2; s++) {           // two k16 steps per 32-half chunk
            unsigned af[4][4], bf[8][2];
            int kb = s * 32 + tg * 4;           // byte offset in row
#pragma unroll
            for (int mi = 0; mi < 4; mi++) {
                int m = wm * 64 + mi * 16 + g;
                af[mi][0] = *(const unsigned*)(As + m * HP + kb);
                af[mi][1] = *(const unsigned*)(As + (m + 8) * HP + kb);
                af[mi][2] = *(const unsigned*)(As + m * HP + kb + 16);
                af[mi][3] = *(const unsigned*)(As + (m + 8) * HP + kb + 16);
            }
#pragma unroll
            for (int ni = 0; ni < 8; ni++) {
                int n = wn * 64 + ni * 8 + g;
                bf[ni][0] = *(const unsigned*)(Bs + n * HP + kb);
                bf[ni][1] = *(const unsigned*)(Bs + n * HP + kb + 16);
            }
#pragma unroll
            for (int mi = 0; mi < 4; mi++)
#pragma unroll
                for (int ni = 0; ni < 8; ni++) {
                    asm volatile(
                        "mma.sync.aligned.m16n8k16.row.col.f32.f16.f16.f32 "
                        "{%0,%1,%2,%3}, {%4,%5,%6,%7}, {%8,%9}, {%0,%1,%2,%3};"
                        : "+f"(acc[mi][ni][0]), "+f"(acc[mi][ni][1]),
                          "+f"(acc[mi][ni][2]), "+f"(acc[mi][ni][3])
                        : "r"(af[mi][0]), "r"(af[mi][1]), "r"(af[mi][2]), "r"(af[mi][3]),
                          "r"(bf[ni][0]), "r"(bf[ni][1]));
                }
        }
    }

    // ---- epilogue: bias (+ optional per-head row softmax), write fp32 ----
    float2 bi[8];
#pragma unroll
    for (int ni = 0; ni < 8; ni++)
        bi[ni] = *(const float2*)(bp + bcol + wn * 64 + ni * 8 + 2 * tg);
#pragma unroll
    for (int mi = 0; mi < 4; mi++)
#pragma unroll
        for (int ni = 0; ni < 8; ni++) {
            acc[mi][ni][0] += bi[ni].x; acc[mi][ni][1] += bi[ni].y;
            acc[mi][ni][2] += bi[ni].x; acc[mi][ni][3] += bi[ni].y;
        }

    if (do_sm) {
        // Row softmax over the warp's 64 cols (= one head). Row owned by the
        // lane-quad g*4+{0..3}; shfl_xor 1,2 stay inside the quad.
#pragma unroll
        for (int mi = 0; mi < 4; mi++)
#pragma unroll
            for (int hf = 0; hf < 2; hf++) {
                float mx = -1e30f;
#pragma unroll
                for (int ni = 0; ni < 8; ni++)
                    mx = fmaxf(mx, fmaxf(acc[mi][ni][hf * 2], acc[mi][ni][hf * 2 + 1]));
                mx = fmaxf(mx, __shfl_xor_sync(0xFFFFFFFFu, mx, 1));
                mx = fmaxf(mx, __shfl_xor_sync(0xFFFFFFFFu, mx, 2));
                float sum = 0.0f;
#pragma unroll
                for (int ni = 0; ni < 8; ni++) {
                    float e0 = __expf(acc[mi][ni][hf * 2]     - mx);
                    float e1 = __expf(acc[mi][ni][hf * 2 + 1] - mx);
                    acc[mi][ni][hf * 2] = e0; acc[mi][ni][hf * 2 + 1] = e1;
                    sum += e0 + e1;
                }
                sum += __shfl_xor_sync(0xFFFFFFFFu, sum, 1);
                sum += __shfl_xor_sync(0xFFFFFFFFu, sum, 2);
                float inv = 1.0f / sum;
#pragma unroll
                for (int ni = 0; ni < 8; ni++) {
                    acc[mi][ni][hf * 2] *= inv; acc[mi][ni][hf * 2 + 1] *= inv;
                }
            }
    }

#pragma unroll
    for (int ni = 0; ni < 8; ni++) {
        int col = bcol + wn * 64 + ni * 8 + 2 * tg;
#pragma unroll
        for (int mi = 0; mi < 4; mi++) {
            long long r0 = brow + wm * 64 + mi * 16 + g;
            *(float2*)(Cp + r0 * N + col)       = make_float2(acc[mi][ni][0], acc[mi][ni][1]);
            *(float2*)(Cp + (r0 + 8) * N + col) = make_float2(acc[mi][ni][2], acc[mi][ni][3]);
        }
    }
}

// ---------------------------------------------------------------------------
// Attention phase 1 (tensor cores, tf32): partial kv + ksum per (pair, split).
// grid = 1024: blockIdx.x = pair*SPLITS + split; each split covers 256 rows.
// (unchanged from Round 13 — measured 57.8us)
// ---------------------------------------------------------------------------
#define KST 72

__global__ __launch_bounds__(256, 1) void attn_p1()
{
    __shared__ float k_s[64 * KST];
    __shared__ float v_s[64 * KST];
    __shared__ float sc_s[64][2];

    const int bx = blockIdx.x;
    const int pair = bx >> 3;
    const int sp = bx & (SPLITS - 1);
    const int b = pair >> 4;
    const int h = pair & 15;
    const int tid = threadIdx.x;
    const int wid = tid >> 5;
    const int lane = tid & 31;
    const int g = lane >> 2;          // 0..7
    const int tg = lane & 3;          // 0..3

    const int m0 = wid * 16;          // feature band base
    const int selA = m0 >> 6;         // 0 = sin, 1 = cos (constant per warp)
    const int dlo = (m0 & 63) + g;    // k dim for rows g, g+8 of the band
    const int dhi = dlo + 8;

    const float* kbase = g_k + ((long long)b * LL) * EE + h * DD;
    const float* vbase = g_v + ((long long)b * LL) * EE + h * DD;

    const float cidx = 1.5707963267948966f / (float)LL;

    float acc[8][4];
#pragma unroll
    for (int ni = 0; ni < 8; ni++)
#pragma unroll
        for (int r = 0; r < 4; r++) acc[ni][r] = 0.0f;
    float ks_sin = 0.0f, ks_cos = 0.0f;

    for (int c = 0; c < LL / SPLITS / 64; c++) {     // 4 chunks of 64 rows
        int l0 = sp * (LL / SPLITS) + c * 64;
        if (tid < 64) {
            float s, co;
            __sincosf(cidx * (float)(l0 + tid + 1), &s, &co);
            sc_s[tid][0] = s; sc_s[tid][1] = co;
        }
#pragma unroll
        for (int i = 0; i < 4; i++) {
            int idx = tid + i * 256;
            int r  = idx >> 4;        // 0..63
            int c4 = idx & 15;
            *(float4*)&k_s[r * KST + c4 * 4] = *(const float4*)(kbase + (long long)(l0 + r) * EE + c4 * 4);
            *(float4*)&v_s[r * KST + c4 * 4] = *(const float4*)(vbase + (long long)(l0 + r) * EE + c4 * 4);
        }
        __syncthreads();

#pragma unroll
        for (int ks = 0; ks < 8; ks++) {
            const int la = ks * 8 + tg;       // k index tg, tg+4 rows
            const float t0 = sc_s[la][selA];
            const float t1 = sc_s[la + 4][selA];
            unsigned a0 = tf32u(k_s[la * KST + dlo] * t0);
            unsigned a1 = tf32u(k_s[la * KST + dhi] * t0);
            unsigned a2 = tf32u(k_s[(la + 4) * KST + dlo] * t1);
            unsigned a3 = tf32u(k_s[(la + 4) * KST + dhi] * t1);
#pragma unroll
            for (int ni = 0; ni < 8; ni++) {
                unsigned b0 = tf32u(v_s[la * KST + ni * 8 + g]);
                unsigned b1 = tf32u(v_s[(la + 4) * KST + ni * 8 + g]);
                asm volatile(
                    "mma.sync.aligned.m16n8k8.row.col.f32.tf32.tf32.f32 "
                    "{%0,%1,%2,%3}, {%4,%5,%6,%7}, {%8,%9}, {%0,%1,%2,%3};"
                    : "+f"(acc[ni][0]), "+f"(acc[ni][1]),
                      "+f"(acc[ni][2]), "+f"(acc[ni][3])
                    : "r"(a0), "r"(a1), "r"(a2), "r"(a3), "r"(b0), "r"(b1));
            }
        }

        if (tid < 64) {
            for (int l = 0; l < 64; l++) {
                float kd = k_s[l * KST + tid];
                ks_sin = fmaf(kd, sc_s[l][0], ks_sin);
                ks_cos = fmaf(kd, sc_s[l][1], ks_cos);
            }
        }
        __syncthreads();
    }

    // epilogue: map fragments into part[d][sel*64 + n] (layout p2 expects)
    float* part = g_part + (long long)bx * PSTRIDE;
    const int d1 = (m0 & 63) + g;          // feature row m0+g
    const int d2 = d1 + 8;                 // feature row m0+g+8
#pragma unroll
    for (int ni = 0; ni < 8; ni++) {
        int n = ni * 8 + 2 * tg;
        *(float2*)&part[d1 * 128 + selA * 64 + n] = make_float2(acc[ni][0], acc[ni][1]);
        *(float2*)&part[d2 * 128 + selA * 64 + n] = make_float2(acc[ni][2], acc[ni][3]);
    }
    if (tid < 64) { part[8192 + tid] = ks_sin; part[8256 + tid] = ks_cos; }
}

// ---------------------------------------------------------------------------
// Attention phase 2 (tensor cores, tf32): grid = 512 (pair*4 + quarter).
// Reduce SPLITS partials -> kv_s[64][136] (cols 0..127 kv, 128/129 ksum,
// 130..135 zero), tf32-rounded in smem. Then 4 chunks of 128 q-rows:
// D[128 rows][136 cols] = q[128x64] @ kv[64x136] via mma.sync.m16n8k8.tf32.
// Cols m & m+64 land in nb/nb+8 of the SAME thread -> in-register combine;
// us/uc (cols 128/129) broadcast from the tg=0 lane of each quad.
// Strides: q 68 (bank g*4+tg), kv 136 (bank tg*8+g) -> conflict-free.
// ---------------------------------------------------------------------------
#define QST 68
#define KVST 136

__global__ __launch_bounds__(256, 1) void attn_p2()
{
    extern __shared__ float sm[];
    __shared__ float vsum_s[128];
    __shared__ float S_s[2];

    float* kv_s = sm;                 // [64][KVST]  = 8704 floats
    float* q_s  = sm + 64 * KVST;     // [128][QST]  = 8704 floats

    const int bx = blockIdx.x;
    const int pair = bx >> 2;
    const int quarter = bx & 3;
    const int b = pair >> 4;
    const int h = pair & 15;
    const int tid = threadIdx.x;
    const int wid = tid >> 5;
    const int lane = tid & 31;
    const int g = lane >> 2;
    const int tg = lane & 3;
    const int m0 = wid * 16;          // row band base (rows m0..m0+15 of chunk)

    const float* pb = g_part + (long long)pair * SPLITS * PSTRIDE;

    // ---- reduce SPLITS partials into kv_s (tf32-rounded) ----
    for (int t = tid; t < 2048; t += 256) {
        int d = t >> 5, m4 = t & 31;
        float4 o = make_float4(0.f, 0.f, 0.f, 0.f);
#pragma unroll
        for (int s = 0; s < SPLITS; s++) {
            float4 a = *(const float4*)(pb + (long long)s * PSTRIDE + t * 4);
            o.x += a.x; o.y += a.y; o.z += a.z; o.w += a.w;
        }
        o.x = tf32f(o.x); o.y = tf32f(o.y); o.z = tf32f(o.z); o.w = tf32f(o.w);
        *(float4*)&kv_s[d * KVST + m4 * 4] = o;
    }
    if (tid < 64) {
        float ss = 0.0f, sc = 0.0f;
#pragma unroll
        for (int s = 0; s < SPLITS; s++) {
            ss += pb[(long long)s * PSTRIDE + 8192 + tid];
            sc += pb[(long long)s * PSTRIDE + 8256 + tid];
        }
        *(float4*)&kv_s[tid * KVST + 128] = make_float4(tf32f(ss), tf32f(sc), 0.f, 0.f);
        *(float4*)&kv_s[tid * KVST + 132] = make_float4(0.f, 0.f, 0.f, 0.f);
    }
    __syncthreads();
    if (tid < 128) {
        float s = 0.0f;
        for (int d = 0; d < 64; d++) s += kv_s[d * KVST + tid];
        vsum_s[tid] = s;
    }
    if (tid < 2) {
        float s = 0.0f;
        for (int d = 0; d < 64; d++) s += kv_s[d * KVST + 128 + tid];
        S_s[tid] = s;
    }
    __syncthreads();

    const float S_sin = S_s[0], S_cos = S_s[1];
    const float cidx = 1.5707963267948966f / (float)LL;
    const float* qbase = g_q + ((long long)b * LL) * EE + h * DD;

    for (int c = 0; c < 4; c++) {
        const int l0 = quarter * 512 + c * 128;
        // load + round q chunk [128][64]
#pragma unroll
        for (int i = 0; i < 8; i++) {
            int idx = tid + i * 256;
            int r = idx >> 4, c4 = idx & 15;
            float4 v = *(const float4*)(qbase + (long long)(l0 + r) * EE + c4 * 4);
            v.x = tf32f(v.x); v.y = tf32f(v.y); v.z = tf32f(v.z); v.w = tf32f(v.w);
            *(float4*)&q_s[r * QST + c4 * 4] = v;
        }
        __syncthreads();

        float acc[17][4];
#pragma unroll
        for (int nb = 0; nb < 17; nb++)
#pragma unroll
            for (int r = 0; r < 4; r++) acc[nb][r] = 0.0f;

        const int r0 = m0 + g;
#pragma unroll
        for (int ks = 0; ks < 8; ks++) {
            const int kk = ks * 8 + tg;
            unsigned a0 = __float_as_uint(q_s[r0 * QST + kk]);
            unsigned a1 = __float_as_uint(q_s[(r0 + 8) * QST + kk]);
            unsigned a2 = __float_as_uint(q_s[r0 * QST + kk + 4]);
            unsigned a3 = __float_as_uint(q_s[(r0 + 8) * QST + kk + 4]);
#pragma unroll
            for (int nb = 0; nb < 17; nb++) {
                unsigned b0 = __float_as_uint(kv_s[kk * KVST + nb * 8 + g]);
                unsigned b1 = __float_as_uint(kv_s[(kk + 4) * KVST + nb * 8 + g]);
                asm volatile(
                    "mma.sync.aligned.m16n8k8.row.col.f32.tf32.tf32.f32 "
                    "{%0,%1,%2,%3}, {%4,%5,%6,%7}, {%8,%9}, {%0,%1,%2,%3};"
                    : "+f"(acc[nb][0]), "+f"(acc[nb][1]),
                      "+f"(acc[nb][2]), "+f"(acc[nb][3])
                    : "r"(a0), "r"(a1), "r"(a2), "r"(a3), "r"(b0), "r"(b1));
            }
        }

        // ---- epilogue: combine sin/cos branches, write fp16 ----
        const int qlead = lane & ~3;           // tg=0 lane of this quad
        float usA = __shfl_sync(0xFFFFFFFFu, acc[16][0], qlead);
        float ucA = __shfl_sync(0xFFFFFFFFu, acc[16][1], qlead);
        float usB = __shfl_sync(0xFFFFFFFFu, acc[16][2], qlead);
        float ucB = __shfl_sync(0xFFFFFFFFu, acc[16][3], qlead);

#pragma unroll
        for (int half = 0; half < 2; half++) {
            const int l = l0 + r0 + half * 8;
            const float us = half ? usB : usA;
            const float uc = half ? ucB : ucA;
            float s, co;
            __sincosf(cidx * (float)(l + 1), &s, &co);
            const float den1 = fmaf(s, us, co * uc);
            const float z1 = 1.0f / fmaxf(den1, EPSF);
            const float den2 = s * (62.0f * S_sin + us) + co * (62.0f * S_cos + uc);
            const float z2 = 1.0f / fmaxf(den2, EPSF);
            __half* op = g_ah + ((long long)l * BB + b) * EE + h * DD;
#pragma unroll
            for (int nb = 0; nb < 8; nb++) {
                const int m = nb * 8 + 2 * tg;
                const float ts0  = acc[nb][half * 2];
                const float ts1  = acc[nb][half * 2 + 1];
                const float tc0  = acc[nb + 8][half * 2];
                const float tc1  = acc[nb + 8][half * 2 + 1];
                float o0 = fmaf(s, ts0, co * tc0) * z1 +
                           (s * (62.0f * vsum_s[m]     + ts0) + co * (62.0f * vsum_s[m + 64]     + tc0)) * z2;
                float o1 = fmaf(s, ts1, co * tc1) * z1 +
                           (s * (62.0f * vsum_s[m + 1] + ts1) + co * (62.0f * vsum_s[m + 65]     + tc1)) * z2;
                __half2 hp = __floats2half2_rn(o0, o1);
                *(__half2*)(op + m) = hp;
            }
        }
        __syncthreads();
    }
}

// ---------------------------------------------------------------------------
extern "C" void kernel_launch(void* const* d_in, const int* in_sizes, int n_in,
                              void* d_out, int out_size)
{
    (void)in_sizes; (void)n_in; (void)out_size;
    const float* X  = (const float*)d_in[0];
    const float* Wq = (const float*)d_in[1];
    const float* bq = (const float*)d_in[2];
    const float* Wk = (const float*)d_in[3];
    const float* bk = (const float*)d_in[4];
    const float* Wv = (const float*)d_in[5];
    const float* bv = (const float*)d_in[6];
    const float* Wo = (const float*)d_in[7];
    const float* bo = (const float*)d_in[8];
    float* out = (float*)d_out;

    float *gq, *gk, *gv;
    __half *gah, *gxh, *gwq, *gwk, *gwv, *gwo;
    cudaGetSymbolAddress((void**)&gq, g_q);
    cudaGetSymbolAddress((void**)&gk, g_k);
    cudaGetSymbolAddress((void**)&gv, g_v);
    cudaGetSymbolAddress((void**)&gah, g_ah);
    cudaGetSymbolAddress((void**)&gxh, g_xh);
    cudaGetSymbolAddress((void**)&gwq, g_wqh);
    cudaGetSymbolAddress((void**)&gwk, g_wkh);
    cudaGetSymbolAddress((void**)&gwv, g_wvh);
    cudaGetSymbolAddress((void**)&gwo, g_woh);

    const int p2smem = (64 * KVST + 128 * QST) * 4;   // 69632 B

    cudaFuncSetAttribute(gemm_h, cudaFuncAttributeMaxDynamicSharedMemorySize, GSMH);
    cudaFuncSetAttribute(attn_p2, cudaFuncAttributeMaxDynamicSharedMemorySize, p2smem);

    // 0) convert X and weights (transposed) to fp16
    conv_x<<<(int)(((long long)MROWS * EE / 8 + 255) / 256), 256>>>(X);
    wtrans_h<<<dim3(32, 32, 4), 256>>>(Wq, Wk, Wv, Wo);

    // 1) fused QKV projections with per-head softmax on q,k in the epilogue
    gemm_h<<<dim3(EE / 256, MROWS / 128, 3), 256, GSMH>>>(
        gxh, gwq, bq, gq, gwk, bk, gk, gwv, bv, gv, 0b011);

    // 2) linear attention: tensor-core phase 1 / phase 2
    attn_p1<<<128 * SPLITS, 256>>>();
    attn_p2<<<128 * 4, 256, p2smem>>>();

    // 3) output projection into d_out (fp16 tensor cores)
    gemm_h<<<dim3(EE / 256, MROWS / 128, 1), 256, GSMH>>>(
        gah, gwo, bo, out, gwo, bo, out, gwo, bo, out, 0);
}

// round 16
// speedup vs baseline: 1.9187x; 1.0110x over previous
#include <cuda_runtime.h>
#include <cuda_fp16.h>
#include <math.h>
#include <stdint.h>

// Problem constants
#define BB 8
#define LL 2048
#define EE 1024
#define HH 16
#define DD 64
#define MROWS (BB*LL)          // 16384
#define EPSF 1e-6f

// Scratch (device globals: allocation-free rule)
__device__ float  g_q[(size_t)MROWS * EE];
__device__ float  g_k[(size_t)MROWS * EE];
__device__ float  g_v[(size_t)MROWS * EE];
__device__ __half g_ah[(size_t)MROWS * EE];      // fp16 attention output (Wo GEMM input)
__device__ __half g_xh[(size_t)MROWS * EE];      // fp16 X
__device__ __half g_wqh[(size_t)EE * EE];        // fp16 transposed weights [N][K]
__device__ __half g_wkh[(size_t)EE * EE];
__device__ __half g_wvh[(size_t)EE * EE];
__device__ __half g_woh[(size_t)EE * EE];
#define SPLITS 8
#define PSTRIDE 8320                              // 64*128 kv + 2*64 ksum
__device__ float  g_part[(size_t)128 * SPLITS * PSTRIDE];   // attn phase-1 partials

__device__ __forceinline__ unsigned tf32u(float x) {
    unsigned u;
    asm("cvt.rna.tf32.f32 %0, %1;" : "=r"(u) : "f"(x));
    return u;
}
__device__ __forceinline__ float tf32f(float x) {
    return __uint_as_float(tf32u(x));
}

// ---------------------------------------------------------------------------
// Conversions
// ---------------------------------------------------------------------------
__global__ __launch_bounds__(256) void conv_x(const float* __restrict__ X)
{
    long long i8 = (long long)blockIdx.x * 256 + threadIdx.x;   // 8 floats each
    long long base = i8 * 8;
    if (base >= (long long)MROWS * EE) return;
    float4 v0 = *(const float4*)(X + base);
    float4 v1 = *(const float4*)(X + base + 4);
    __half2 h[4];
    h[0] = __floats2half2_rn(v0.x, v0.y);
    h[1] = __floats2half2_rn(v0.z, v0.w);
    h[2] = __floats2half2_rn(v1.x, v1.y);
    h[3] = __floats2half2_rn(v1.z, v1.w);
    *(uint4*)(g_xh + base) = *(uint4*)h;
}

// Weight transpose + fp16 round: Wt[n][k] = rn(W[k][n]). 32x32 tiles.
__global__ __launch_bounds__(256) void wtrans_h(
    const float* __restrict__ Wq, const float* __restrict__ Wk,
    const float* __restrict__ Wv, const float* __restrict__ Wo)
{
    __shared__ float t[32][33];
    const float* W; __half* Wt;
    switch (blockIdx.z) {
        case 0: W = Wq; Wt = g_wqh; break;
        case 1: W = Wk; Wt = g_wkh; break;
        case 2: W = Wv; Wt = g_wvh; break;
        default: W = Wo; Wt = g_woh; break;
    }
    int tx = threadIdx.x & 31, ty = threadIdx.x >> 5;   // 32 x 8
    int k0 = blockIdx.y * 32, n0 = blockIdx.x * 32;
#pragma unroll
    for (int i = 0; i < 4; i++)
        t[ty + i * 8][tx] = W[(long long)(k0 + ty + i * 8) * EE + n0 + tx];
    __syncthreads();
#pragma unroll
    for (int i = 0; i < 4; i++)
        Wt[(long long)(n0 + ty + i * 8) * EE + k0 + tx] = __float2half_rn(t[tx][ty + i * 8]);
}

// ---------------------------------------------------------------------------
// fp16 tensor-core GEMM: C = A(MxK) @ Wt(NxK)^T + bias, fp32 accum/output.
// CTA tile 128x256, BK=32 halves, 256 threads (8 warps, each 64x64).
// mma.sync.m16n8k16 + ldmatrix.x4 fragment loads (4x fewer smem instr than
// scalar LDS). 3-stage cp.async pipeline, ONE barrier per chunk.
// smask bit z: per-head row softmax (D=64) in the epilogue.
// ---------------------------------------------------------------------------
#define HP 80                     // bytes per smem row
#define ASTG (128*HP)             // 10240
#define BSTG (256*HP)             // 20480
#define STGH (ASTG+BSTG)          // 30720
#define GSMH (3*STGH)             // 92160
#define NCH 32                    // 1024/32 chunks

__device__ __forceinline__ void cp16(void* dst, const void* src) {
    unsigned d = (unsigned)__cvta_generic_to_shared(dst);
    asm volatile("cp.async.cg.shared.global [%0], [%1], 16;\n" :: "r"(d), "l"(src) : "memory");
}

__device__ __forceinline__ void ldsm_x4(unsigned* r, unsigned addr) {
    asm volatile("ldmatrix.sync.aligned.m8n8.x4.shared.b16 {%0,%1,%2,%3}, [%4];"
                 : "=r"(r[0]), "=r"(r[1]), "=r"(r[2]), "=r"(r[3]) : "r"(addr));
}

__global__ __launch_bounds__(256, 1) void gemm_h(
    const __half* __restrict__ A,
    const __half* __restrict__ W0, const float* __restrict__ b0, float* __restrict__ C0,
    const __half* __restrict__ W1, const float* __restrict__ b1, float* __restrict__ C1,
    const __half* __restrict__ W2, const float* __restrict__ b2, float* __restrict__ C2,
    int smask)
{
    constexpr int K = EE;
    constexpr int N = EE;
    const __half* Wp = W0; const float* bp = b0; float* Cp = C0;
    if (blockIdx.z == 1) { Wp = W1; bp = b1; Cp = C1; }
    else if (blockIdx.z == 2) { Wp = W2; bp = b2; Cp = C2; }
    const bool do_sm = (smask >> blockIdx.z) & 1;

    extern __shared__ char smc[];

    const int tid = threadIdx.x;
    const int wid = tid >> 5;
    const int lane = tid & 31;
    const int g = lane >> 2;       // 0..7
    const int tg = lane & 3;       // 0..3
    const int wm = wid & 1;
    const int wn = wid >> 1;

    const long long brow = (long long)blockIdx.y * 128;
    const int bcol = blockIdx.x * 256;

    const __half* Abase = A + brow * K;
    const __half* Bbase = Wp + (long long)bcol * K;

    // per-lane ldmatrix row/col offsets (within a stage)
    const unsigned smem0 = (unsigned)__cvta_generic_to_shared(smc);
    // A tile (16x16): lanes 0-15 rows m..m+15 (k-half 0), lanes 16-31 same rows k-half 1
    const unsigned a_off = (unsigned)((wm * 64 + (lane & 15)) * HP + (lane >> 4) * 16);
    // B tile (16 n-rows x 16 k): lanes 0-7 n..n+7 kh0, 8-15 n..n+7 kh1,
    //                            16-23 n+8..n+15 kh0, 24-31 n+8..n+15 kh1
    const unsigned b_off = (unsigned)(ASTG +
        (wn * 64 + (lane & 7) + ((lane & 16) ? 8 : 0)) * HP + ((lane & 8) ? 16 : 0));

    float acc[4][8][4];
#pragma unroll
    for (int mi = 0; mi < 4; mi++)
#pragma unroll
        for (int ni = 0; ni < 8; ni++)
#pragma unroll
            for (int r = 0; r < 4; r++) acc[mi][ni][r] = 0.0f;

    auto load_chunk = [&](int ch) {
        char* As = smc + (ch % 3) * STGH;
        char* Bs = As + ASTG;
        const __half* Ag = Abase + ch * 32;
        const __half* Bg = Bbase + ch * 32;
#pragma unroll
        for (int i = 0; i < 2; i++) {           // A: 128 rows x 4 granules
            int idx = tid + i * 256;
            int r = idx >> 2, c = idx & 3;
            cp16(As + r * HP + c * 16, Ag + (long long)r * K + c * 8);
        }
#pragma unroll
        for (int i = 0; i < 4; i++) {           // B: 256 rows x 4 granules
            int idx = tid + i * 256;
            int r = idx >> 2, c = idx & 3;
            cp16(Bs + r * HP + c * 16, Bg + (long long)r * K + c * 8);
        }
        asm volatile("cp.async.commit_group;\n" ::: "memory");
    };

    load_chunk(0);
    load_chunk(1);

    for (int c = 0; c < NCH; c++) {
        if (c + 1 < NCH) asm volatile("cp.async.wait_group 1;\n" ::: "memory");
        else             asm volatile("cp.async.wait_group 0;\n" ::: "memory");
        __syncthreads();
        // Safe to overwrite stage (c+2)%3 == (c-1)%3: the barrier above proves
        // every warp finished its mma reads of chunk c-1 (issued last iter).
        if (c + 2 < NCH) load_chunk(c + 2);

        const unsigned stg = smem0 + (unsigned)((c % 3) * STGH);

#pragma unroll
        for (int s = 0; s < 2; s++) {           // two k16 steps per 32-half chunk
            unsigned af[4][4], bf[8][2];
            const unsigned kadd = (unsigned)(s * 32);
#pragma unroll
            for (int mi = 0; mi < 4; mi++)
                ldsm_x4(af[mi], stg + a_off + (unsigned)(mi * 16 * HP) + kadd);
#pragma unroll
            for (int nb = 0; nb < 4; nb++) {
                unsigned t[4];
                ldsm_x4(t, stg + b_off + (unsigned)(nb * 16 * HP) + kadd);
                bf[nb * 2][0] = t[0]; bf[nb * 2][1] = t[1];
                bf[nb * 2 + 1][0] = t[2]; bf[nb * 2 + 1][1] = t[3];
            }
#pragma unroll
            for (int mi = 0; mi < 4; mi++)
#pragma unroll
                for (int ni = 0; ni < 8; ni++) {
                    asm volatile(
                        "mma.sync.aligned.m16n8k16.row.col.f32.f16.f16.f32 "
                        "{%0,%1,%2,%3}, {%4,%5,%6,%7}, {%8,%9}, {%0,%1,%2,%3};"
                        : "+f"(acc[mi][ni][0]), "+f"(acc[mi][ni][1]),
                          "+f"(acc[mi][ni][2]), "+f"(acc[mi][ni][3])
                        : "r"(af[mi][0]), "r"(af[mi][1]), "r"(af[mi][2]), "r"(af[mi][3]),
                          "r"(bf[ni][0]), "r"(bf[ni][1]));
                }
        }
    }

    // ---- epilogue: bias (+ optional per-head row softmax), write fp32 ----
    float2 bi[8];
#pragma unroll
    for (int ni = 0; ni < 8; ni++)
        bi[ni] = *(const float2*)(bp + bcol + wn * 64 + ni * 8 + 2 * tg);
#pragma unroll
    for (int mi = 0; mi < 4; mi++)
#pragma unroll
        for (int ni = 0; ni < 8; ni++) {
            acc[mi][ni][0] += bi[ni].x; acc[mi][ni][1] += bi[ni].y;
            acc[mi][ni][2] += bi[ni].x; acc[mi][ni][3] += bi[ni].y;
        }

    if (do_sm) {
        // Row softmax over the warp's 64 cols (= one head). Row owned by the
        // lane-quad g*4+{0..3}; shfl_xor 1,2 stay inside the quad.
#pragma unroll
        for (int mi = 0; mi < 4; mi++)
#pragma unroll
            for (int hf = 0; hf < 2; hf++) {
                float mx = -1e30f;
#pragma unroll
                for (int ni = 0; ni < 8; ni++)
                    mx = fmaxf(mx, fmaxf(acc[mi][ni][hf * 2], acc[mi][ni][hf * 2 + 1]));
                mx = fmaxf(mx, __shfl_xor_sync(0xFFFFFFFFu, mx, 1));
                mx = fmaxf(mx, __shfl_xor_sync(0xFFFFFFFFu, mx, 2));
                float sum = 0.0f;
#pragma unroll
                for (int ni = 0; ni < 8; ni++) {
                    float e0 = __expf(acc[mi][ni][hf * 2]     - mx);
                    float e1 = __expf(acc[mi][ni][hf * 2 + 1] - mx);
                    acc[mi][ni][hf * 2] = e0; acc[mi][ni][hf * 2 + 1] = e1;
                    sum += e0 + e1;
                }
                sum += __shfl_xor_sync(0xFFFFFFFFu, sum, 1);
                sum += __shfl_xor_sync(0xFFFFFFFFu, sum, 2);
                float inv = 1.0f / sum;
#pragma unroll
                for (int ni = 0; ni < 8; ni++) {
                    acc[mi][ni][hf * 2] *= inv; acc[mi][ni][hf * 2 + 1] *= inv;
                }
            }
    }

#pragma unroll
    for (int ni = 0; ni < 8; ni++) {
        int col = bcol + wn * 64 + ni * 8 + 2 * tg;
#pragma unroll
        for (int mi = 0; mi < 4; mi++) {
            long long r0 = brow + wm * 64 + mi * 16 + g;
            *(float2*)(Cp + r0 * N + col)       = make_float2(acc[mi][ni][0], acc[mi][ni][1]);
            *(float2*)(Cp + (r0 + 8) * N + col) = make_float2(acc[mi][ni][2], acc[mi][ni][3]);
        }
    }
}

// ---------------------------------------------------------------------------
// Attention phase 1 (tensor cores, tf32): partial kv + ksum per (pair, split).
// grid = 1024: blockIdx.x = pair*SPLITS + split; each split covers 256 rows.
// (unchanged — measured 56.8us)
// ---------------------------------------------------------------------------
#define KST 72

__global__ __launch_bounds__(256, 1) void attn_p1()
{
    __shared__ float k_s[64 * KST];
    __shared__ float v_s[64 * KST];
    __shared__ float sc_s[64][2];

    const int bx = blockIdx.x;
    const int pair = bx >> 3;
    const int sp = bx & (SPLITS - 1);
    const int b = pair >> 4;
    const int h = pair & 15;
    const int tid = threadIdx.x;
    const int wid = tid >> 5;
    const int lane = tid & 31;
    const int g = lane >> 2;          // 0..7
    const int tg = lane & 3;          // 0..3

    const int m0 = wid * 16;          // feature band base
    const int selA = m0 >> 6;         // 0 = sin, 1 = cos (constant per warp)
    const int dlo = (m0 & 63) + g;    // k dim for rows g, g+8 of the band
    const int dhi = dlo + 8;

    const float* kbase = g_k + ((long long)b * LL) * EE + h * DD;
    const float* vbase = g_v + ((long long)b * LL) * EE + h * DD;

    const float cidx = 1.5707963267948966f / (float)LL;

    float acc[8][4];
#pragma unroll
    for (int ni = 0; ni < 8; ni++)
#pragma unroll
        for (int r = 0; r < 4; r++) acc[ni][r] = 0.0f;
    float ks_sin = 0.0f, ks_cos = 0.0f;

    for (int c = 0; c < LL / SPLITS / 64; c++) {     // 4 chunks of 64 rows
        int l0 = sp * (LL / SPLITS) + c * 64;
        if (tid < 64) {
            float s, co;
            __sincosf(cidx * (float)(l0 + tid + 1), &s, &co);
            sc_s[tid][0] = s; sc_s[tid][1] = co;
        }
#pragma unroll
        for (int i = 0; i < 4; i++) {
            int idx = tid + i * 256;
            int r  = idx >> 4;        // 0..63
            int c4 = idx & 15;
            *(float4*)&k_s[r * KST + c4 * 4] = *(const float4*)(kbase + (long long)(l0 + r) * EE + c4 * 4);
            *(float4*)&v_s[r * KST + c4 * 4] = *(const float4*)(vbase + (long long)(l0 + r) * EE + c4 * 4);
        }
        __syncthreads();

#pragma unroll
        for (int ks = 0; ks < 8; ks++) {
            const int la = ks * 8 + tg;       // k index tg, tg+4 rows
            const float t0 = sc_s[la][selA];
            const float t1 = sc_s[la + 4][selA];
            unsigned a0 = tf32u(k_s[la * KST + dlo] * t0);
            unsigned a1 = tf32u(k_s[la * KST + dhi] * t0);
            unsigned a2 = tf32u(k_s[(la + 4) * KST + dlo] * t1);
            unsigned a3 = tf32u(k_s[(la + 4) * KST + dhi] * t1);
#pragma unroll
            for (int ni = 0; ni < 8; ni++) {
                unsigned b0 = tf32u(v_s[la * KST + ni * 8 + g]);
                unsigned b1 = tf32u(v_s[(la + 4) * KST + ni * 8 + g]);
                asm volatile(
                    "mma.sync.aligned.m16n8k8.row.col.f32.tf32.tf32.f32 "
                    "{%0,%1,%2,%3}, {%4,%5,%6,%7}, {%8,%9}, {%0,%1,%2,%3};"
                    : "+f"(acc[ni][0]), "+f"(acc[ni][1]),
                      "+f"(acc[ni][2]), "+f"(acc[ni][3])
                    : "r"(a0), "r"(a1), "r"(a2), "r"(a3), "r"(b0), "r"(b1));
            }
        }

        if (tid < 64) {
            for (int l = 0; l < 64; l++) {
                float kd = k_s[l * KST + tid];
                ks_sin = fmaf(kd, sc_s[l][0], ks_sin);
                ks_cos = fmaf(kd, sc_s[l][1], ks_cos);
            }
        }
        __syncthreads();
    }

    // epilogue: map fragments into part[d][sel*64 + n] (layout p2 expects)
    float* part = g_part + (long long)bx * PSTRIDE;
    const int d1 = (m0 & 63) + g;          // feature row m0+g
    const int d2 = d1 + 8;                 // feature row m0+g+8
#pragma unroll
    for (int ni = 0; ni < 8; ni++) {
        int n = ni * 8 + 2 * tg;
        *(float2*)&part[d1 * 128 + selA * 64 + n] = make_float2(acc[ni][0], acc[ni][1]);
        *(float2*)&part[d2 * 128 + selA * 64 + n] = make_float2(acc[ni][2], acc[ni][3]);
    }
    if (tid < 64) { part[8192 + tid] = ks_sin; part[8256 + tid] = ks_cos; }
}

// ---------------------------------------------------------------------------
// Attention phase 2 (tensor cores, tf32): grid = 512 (pair*4 + quarter).
// (unchanged from Round 15)
// ---------------------------------------------------------------------------
#define QST 68
#define KVST 136

__global__ __launch_bounds__(256, 1) void attn_p2()
{
    extern __shared__ float sm[];
    __shared__ float vsum_s[128];
    __shared__ float S_s[2];

    float* kv_s = sm;                 // [64][KVST]  = 8704 floats
    float* q_s  = sm + 64 * KVST;     // [128][QST]  = 8704 floats

    const int bx = blockIdx.x;
    const int pair = bx >> 2;
    const int quarter = bx & 3;
    const int b = pair >> 4;
    const int h = pair & 15;
    const int tid = threadIdx.x;
    const int wid = tid >> 5;
    const int lane = tid & 31;
    const int g = lane >> 2;
    const int tg = lane & 3;
    const int m0 = wid * 16;          // row band base (rows m0..m0+15 of chunk)

    const float* pb = g_part + (long long)pair * SPLITS * PSTRIDE;

    // ---- reduce SPLITS partials into kv_s (tf32-rounded) ----
    for (int t = tid; t < 2048; t += 256) {
        int d = t >> 5, m4 = t & 31;
        float4 o = make_float4(0.f, 0.f, 0.f, 0.f);
#pragma unroll
        for (int s = 0; s < SPLITS; s++) {
            float4 a = *(const float4*)(pb + (long long)s * PSTRIDE + t * 4);
            o.x += a.x; o.y += a.y; o.z += a.z; o.w += a.w;
        }
        o.x = tf32f(o.x); o.y = tf32f(o.y); o.z = tf32f(o.z); o.w = tf32f(o.w);
        *(float4*)&kv_s[d * KVST + m4 * 4] = o;
    }
    if (tid < 64) {
        float ss = 0.0f, sc = 0.0f;
#pragma unroll
        for (int s = 0; s < SPLITS; s++) {
            ss += pb[(long long)s * PSTRIDE + 8192 + tid];
            sc += pb[(long long)s * PSTRIDE + 8256 + tid];
        }
        *(float4*)&kv_s[tid * KVST + 128] = make_float4(tf32f(ss), tf32f(sc), 0.f, 0.f);
        *(float4*)&kv_s[tid * KVST + 132] = make_float4(0.f, 0.f, 0.f, 0.f);
    }
    __syncthreads();
    if (tid < 128) {
        float s = 0.0f;
        for (int d = 0; d < 64; d++) s += kv_s[d * KVST + tid];
        vsum_s[tid] = s;
    }
    if (tid < 2) {
        float s = 0.0f;
        for (int d = 0; d < 64; d++) s += kv_s[d * KVST + 128 + tid];
        S_s[tid] = s;
    }
    __syncthreads();

    const float S_sin = S_s[0], S_cos = S_s[1];
    const float cidx = 1.5707963267948966f / (float)LL;
    const float* qbase = g_q + ((long long)b * LL) * EE + h * DD;

    for (int c = 0; c < 4; c++) {
        const int l0 = quarter * 512 + c * 128;
        // load + round q chunk [128][64]
#pragma unroll
        for (int i = 0; i < 8; i++) {
            int idx = tid + i * 256;
            int r = idx >> 4, c4 = idx & 15;
            float4 v = *(const float4*)(qbase + (long long)(l0 + r) * EE + c4 * 4);
            v.x = tf32f(v.x); v.y = tf32f(v.y); v.z = tf32f(v.z); v.w = tf32f(v.w);
            *(float4*)&q_s[r * QST + c4 * 4] = v;
        }
        __syncthreads();

        float acc[17][4];
#pragma unroll
        for (int nb = 0; nb < 17; nb++)
#pragma unroll
            for (int r = 0; r < 4; r++) acc[nb][r] = 0.0f;

        const int r0 = m0 + g;
#pragma unroll
        for (int ks = 0; ks < 8; ks++) {
            const int kk = ks * 8 + tg;
            unsigned a0 = __float_as_uint(q_s[r0 * QST + kk]);
            unsigned a1 = __float_as_uint(q_s[(r0 + 8) * QST + kk]);
            unsigned a2 = __float_as_uint(q_s[r0 * QST + kk + 4]);
            unsigned a3 = __float_as_uint(q_s[(r0 + 8) * QST + kk + 4]);
#pragma unroll
            for (int nb = 0; nb < 17; nb++) {
                unsigned b0 = __float_as_uint(kv_s[kk * KVST + nb * 8 + g]);
                unsigned b1 = __float_as_uint(kv_s[(kk + 4) * KVST + nb * 8 + g]);
                asm volatile(
                    "mma.sync.aligned.m16n8k8.row.col.f32.tf32.tf32.f32 "
                    "{%0,%1,%2,%3}, {%4,%5,%6,%7}, {%8,%9}, {%0,%1,%2,%3};"
                    : "+f"(acc[nb][0]), "+f"(acc[nb][1]),
                      "+f"(acc[nb][2]), "+f"(acc[nb][3])
                    : "r"(a0), "r"(a1), "r"(a2), "r"(a3), "r"(b0), "r"(b1));
            }
        }

        // ---- epilogue: combine sin/cos branches, write fp16 ----
        const int qlead = lane & ~3;           // tg=0 lane of this quad
        float usA = __shfl_sync(0xFFFFFFFFu, acc[16][0], qlead);
        float ucA = __shfl_sync(0xFFFFFFFFu, acc[16][1], qlead);
        float usB = __shfl_sync(0xFFFFFFFFu, acc[16][2], qlead);
        float ucB = __shfl_sync(0xFFFFFFFFu, acc[16][3], qlead);

#pragma unroll
        for (int half = 0; half < 2; half++) {
            const int l = l0 + r0 + half * 8;
            const float us = half ? usB : usA;
            const float uc = half ? ucB : ucA;
            float s, co;
            __sincosf(cidx * (float)(l + 1), &s, &co);
            const float den1 = fmaf(s, us, co * uc);
            const float z1 = 1.0f / fmaxf(den1, EPSF);
            const float den2 = s * (62.0f * S_sin + us) + co * (62.0f * S_cos + uc);
            const float z2 = 1.0f / fmaxf(den2, EPSF);
            __half* op = g_ah + ((long long)l * BB + b) * EE + h * DD;
#pragma unroll
            for (int nb = 0; nb < 8; nb++) {
                const int m = nb * 8 + 2 * tg;
                const float ts0  = acc[nb][half * 2];
                const float ts1  = acc[nb][half * 2 + 1];
                const float tc0  = acc[nb + 8][half * 2];
                const float tc1  = acc[nb + 8][half * 2 + 1];
                float o0 = fmaf(s, ts0, co * tc0) * z1 +
                           (s * (62.0f * vsum_s[m]     + ts0) + co * (62.0f * vsum_s[m + 64]     + tc0)) * z2;
                float o1 = fmaf(s, ts1, co * tc1) * z1 +
                           (s * (62.0f * vsum_s[m + 1] + ts1) + co * (62.0f * vsum_s[m + 65]     + tc1)) * z2;
                __half2 hp = __floats2half2_rn(o0, o1);
                *(__half2*)(op + m) = hp;
            }
        }
        __syncthreads();
    }
}

// ---------------------------------------------------------------------------
extern "C" void kernel_launch(void* const* d_in, const int* in_sizes, int n_in,
                              void* d_out, int out_size)
{
    (void)in_sizes; (void)n_in; (void)out_size;
    const float* X  = (const float*)d_in[0];
    const float* Wq = (const float*)d_in[1];
    const float* bq = (const float*)d_in[2];
    const float* Wk = (const float*)d_in[3];
    const float* bk = (const float*)d_in[4];
    const float* Wv = (const float*)d_in[5];
    const float* bv = (const float*)d_in[6];
    const float* Wo = (const float*)d_in[7];
    const float* bo = (const float*)d_in[8];
    float* out = (float*)d_out;

    float *gq, *gk, *gv;
    __half *gah, *gxh, *gwq, *gwk, *gwv, *gwo;
    cudaGetSymbolAddress((void**)&gq, g_q);
    cudaGetSymbolAddress((void**)&gk, g_k);
    cudaGetSymbolAddress((void**)&gv, g_v);
    cudaGetSymbolAddress((void**)&gah, g_ah);
    cudaGetSymbolAddress((void**)&gxh, g_xh);
    cudaGetSymbolAddress((void**)&gwq, g_wqh);
    cudaGetSymbolAddress((void**)&gwk, g_wkh);
    cudaGetSymbolAddress((void**)&gwv, g_wvh);
    cudaGetSymbolAddress((void**)&gwo, g_woh);

    const int p2smem = (64 * KVST + 128 * QST) * 4;   // 69632 B

    cudaFuncSetAttribute(gemm_h, cudaFuncAttributeMaxDynamicSharedMemorySize, GSMH);
    cudaFuncSetAttribute(attn_p2, cudaFuncAttributeMaxDynamicSharedMemorySize, p2smem);

    // 0) convert X and weights (transposed) to fp16
    conv_x<<<(int)(((long long)MROWS * EE / 8 + 255) / 256), 256>>>(X);
    wtrans_h<<<dim3(32, 32, 4), 256>>>(Wq, Wk, Wv, Wo);

    // 1) fused QKV projections with per-head softmax on q,k in the epilogue
    gemm_h<<<dim3(EE / 256, MROWS / 128, 3), 256, GSMH>>>(
        gxh, gwq, bq, gq, gwk, bk, gk, gwv, bv, gv, 0b011);

    // 2) linear attention: tensor-core phase 1 / phase 2
    attn_p1<<<128 * SPLITS, 256>>>();
    attn_p2<<<128 * 4, 256, p2smem>>>();

    // 3) output projection into d_out (fp16 tensor cores)
    gemm_h<<<dim3(EE / 256, MROWS / 128, 1), 256, GSMH>>>(
        gah, gwo, bo, out, gwo, bo, out, gwo, bo, out, 0);
}